// round 14
// baseline (speedup 1.0000x reference)
#include <cuda_runtime.h>
#include <cuda_bf16.h>
#include <cstdint>
#include <math.h>

// Problem constants
#define BB 2
#define SS 4096
#define DD 1024
#define HH 16
#define HD 64
#define MM (BB * SS)   // 8192

// ---------------------------------------------------------------------------
// Scratch (device globals)
// ---------------------------------------------------------------------------
__device__ __nv_bfloat16 g_Xh[MM * DD];
__device__ __nv_bfloat16 g_Xl[MM * DD];
__device__ __nv_bfloat16 g_Wht[4 * DD * DD];
__device__ __nv_bfloat16 g_Wlt[4 * DD * DD];
__device__ __nv_bfloat16 g_Qh[MM * DD];
__device__ __nv_bfloat16 g_Ql[MM * DD];
__device__ __nv_bfloat16 g_Kh[MM * DD];
__device__ __nv_bfloat16 g_Kl[MM * DD];
__device__ __nv_bfloat16 g_Vh[MM * DD];
__device__ __nv_bfloat16 g_Vl[MM * DD];
__device__ __nv_bfloat16 g_Ah[MM * DD];
__device__ __nv_bfloat16 g_Al[MM * DD];

// ---------------------------------------------------------------------------
// PTX helpers
// ---------------------------------------------------------------------------
__device__ __forceinline__ uint32_t smem_to_u32(const void* p) {
    uint32_t a;
    asm("{ .reg .u64 t; cvta.to.shared.u64 t, %1; cvt.u32.u64 %0, t; }"
        : "=r"(a) : "l"(p));
    return a;
}

__device__ __forceinline__ float ex2(float x) {
    float y;
    asm("ex2.approx.f32 %0, %1;" : "=f"(y) : "f"(x));
    return y;
}

__device__ __forceinline__ void cp_async16(uint32_t dst, const void* src) {
    asm volatile("cp.async.cg.shared.global [%0], [%1], 16;"
                 :: "r"(dst), "l"(src));
}
#define CP_COMMIT() asm volatile("cp.async.commit_group;" ::: "memory")
#define CP_WAIT1()  asm volatile("cp.async.wait_group 1;" ::: "memory")
#define CP_WAIT0()  asm volatile("cp.async.wait_group 0;" ::: "memory")

__device__ __forceinline__ void ldsm_x4(uint32_t& r0, uint32_t& r1,
                                        uint32_t& r2, uint32_t& r3, uint32_t addr) {
    asm volatile("ldmatrix.sync.aligned.m8n8.x4.shared.b16 {%0,%1,%2,%3}, [%4];"
                 : "=r"(r0), "=r"(r1), "=r"(r2), "=r"(r3) : "r"(addr));
}

__device__ __forceinline__ void ldsm_x4t(uint32_t& r0, uint32_t& r1,
                                         uint32_t& r2, uint32_t& r3, uint32_t addr) {
    asm volatile("ldmatrix.sync.aligned.m8n8.x4.trans.shared.b16 {%0,%1,%2,%3}, [%4];"
                 : "=r"(r0), "=r"(r1), "=r"(r2), "=r"(r3) : "r"(addr));
}

__device__ __forceinline__ void mma16816(float* c, const uint32_t* a, const uint32_t* b) {
    asm volatile(
        "mma.sync.aligned.m16n8k16.row.col.f32.bf16.bf16.f32 "
        "{%0,%1,%2,%3}, {%4,%5,%6,%7}, {%8,%9}, {%0,%1,%2,%3};"
        : "+f"(c[0]), "+f"(c[1]), "+f"(c[2]), "+f"(c[3])
        : "r"(a[0]), "r"(a[1]), "r"(a[2]), "r"(a[3]), "r"(b[0]), "r"(b[1]));
}

// ---------------------------------------------------------------------------
// hi/lo bf16 split of X
// ---------------------------------------------------------------------------
__global__ void __launch_bounds__(256) xsplit_kernel(
    const float* __restrict__ X,
    __nv_bfloat16* __restrict__ Xh, __nv_bfloat16* __restrict__ Xl)
{
    int i = (blockIdx.x * 256 + threadIdx.x) * 4;
    float4 v = *(const float4*)(X + i);
    __nv_bfloat162 hp0 = __floats2bfloat162_rn(v.x, v.y);
    __nv_bfloat162 hp1 = __floats2bfloat162_rn(v.z, v.w);
    __nv_bfloat162 lp0 = __floats2bfloat162_rn(v.x - __bfloat162float(hp0.x),
                                               v.y - __bfloat162float(hp0.y));
    __nv_bfloat162 lp1 = __floats2bfloat162_rn(v.z - __bfloat162float(hp1.x),
                                               v.w - __bfloat162float(hp1.y));
    *(__nv_bfloat162*)(Xh + i)     = hp0;
    *(__nv_bfloat162*)(Xh + i + 2) = hp1;
    *(__nv_bfloat162*)(Xl + i)     = lp0;
    *(__nv_bfloat162*)(Xl + i + 2) = lp1;
}

// ---------------------------------------------------------------------------
// Transpose + split all 4 weights
// ---------------------------------------------------------------------------
__global__ void __launch_bounds__(256) wsplit4_kernel(
    const float* __restrict__ W0, const float* __restrict__ W1,
    const float* __restrict__ W2, const float* __restrict__ W3)
{
    __shared__ float t[32][33];
    const int z = blockIdx.z;
    const float* W = (z == 0) ? W0 : (z == 1) ? W1 : (z == 2) ? W2 : W3;
    __nv_bfloat16* Wht = g_Wht + (size_t)z * DD * DD;
    __nv_bfloat16* Wlt = g_Wlt + (size_t)z * DD * DD;

    int tx = threadIdx.x, ty = threadIdx.y;
    int n0 = blockIdx.x * 32, k0 = blockIdx.y * 32;
#pragma unroll
    for (int i = 0; i < 4; i++)
        t[ty + i * 8][tx] = W[(size_t)(k0 + ty + i * 8) * DD + n0 + tx];
    __syncthreads();
#pragma unroll
    for (int i = 0; i < 4; i++) {
        float v = t[tx][ty + i * 8];
        __nv_bfloat16 h = __float2bfloat16_rn(v);
        __nv_bfloat16 l = __float2bfloat16_rn(v - __bfloat162float(h));
        size_t idx = (size_t)(n0 + ty + i * 8) * DD + k0 + tx;
        Wht[idx] = h;
        Wlt[idx] = l;
    }
}

// ---------------------------------------------------------------------------
// GEMM mainloop: 128x128 CTA tile, 256 threads, KC=16, 3-stage cp.async ring,
//   2 CTAs/SM, ONE barrier per chunk. 8 warps: wm {0,1} x wn {0..3}.
// ---------------------------------------------------------------------------
#define KC 16
#define GSTRIDE 24                       // 16 data + 8 pad (48B rows, conflict-free)
#define GTILE_B (128 * GSTRIDE * 2)      // 6144 per array
#define GSTAGE_B (4 * GTILE_B)           // 24576 per stage
#define GEMM_SMEM (3 * GSTAGE_B)         // 73728 -> 2 CTAs/SM
#define NCHUNK 64

__device__ __forceinline__ void gemm_mainloop(
    uint32_t smem_u, int tid, int lane, int wm, int wn,
    const __nv_bfloat16* ah_g, const __nv_bfloat16* al_g,
    const __nv_bfloat16* bh_g, const __nv_bfloat16* bl_g,
    float acc[4][4][4])
{
    const __nv_bfloat16* srcs[4] = { ah_g, al_g, bh_g, bl_g };

    auto issue_chunk = [&](int c) {
        const uint32_t boff = smem_u + (uint32_t)(c % 3) * GSTAGE_B;
        // 4 arrays x 128 rows x 2 groups (8 bf16) = 1024 segs / 256 thr
#pragma unroll
        for (int i = 0; i < 4; i++) {
            int seg = tid + i * 256;
            int arr = seg >> 8;            // 0..3
            int rem = seg & 255;
            int row = rem >> 1, g = rem & 1;
            cp_async16(boff + (uint32_t)arr * GTILE_B
                       + (uint32_t)(row * GSTRIDE + g * 8) * 2,
                       srcs[arr] + (size_t)row * DD + c * KC + g * 8);
        }
    };

    const int a_row = wm * 64 + (lane & 15);
    const int a_kof = (lane >> 4) * 8;
    const int b_row = wn * 32 + (lane & 7) + (lane >> 4) * 8;
    const int b_kof = ((lane >> 3) & 1) * 8;

    issue_chunk(0); CP_COMMIT();
    issue_chunk(1); CP_COMMIT();

    for (int c = 0; c < NCHUNK; c++) {
        if (c < NCHUNK - 1) CP_WAIT1();
        else                CP_WAIT0();
        __syncthreads();                  // chunk c arrived; round c-1 reads done
        if (c + 2 < NCHUNK) { issue_chunk(c + 2); CP_COMMIT(); }

        const uint32_t boff = smem_u + (uint32_t)(c % 3) * GSTAGE_B;
        const uint32_t tAh = boff;
        const uint32_t tAl = boff + GTILE_B;
        const uint32_t tBh = boff + 2 * GTILE_B;
        const uint32_t tBl = boff + 3 * GTILE_B;

        uint32_t bh[4][2], bl[4][2];
#pragma unroll
        for (int p = 0; p < 2; p++) {
            uint32_t bo = (uint32_t)((p * 16 + b_row) * GSTRIDE + b_kof) * 2;
            ldsm_x4(bh[2 * p][0], bh[2 * p][1], bh[2 * p + 1][0], bh[2 * p + 1][1], tBh + bo);
            ldsm_x4(bl[2 * p][0], bl[2 * p][1], bl[2 * p + 1][0], bl[2 * p + 1][1], tBl + bo);
        }
#pragma unroll
        for (int mi = 0; mi < 4; mi++) {
            uint32_t ah[4], al[4];
            uint32_t ao = (uint32_t)((a_row + mi * 16) * GSTRIDE + a_kof) * 2;
            ldsm_x4(ah[0], ah[1], ah[2], ah[3], tAh + ao);
            ldsm_x4(al[0], al[1], al[2], al[3], tAl + ao);
#pragma unroll
            for (int ni = 0; ni < 4; ni++)
                mma16816(acc[mi][ni], ah, bh[ni]);   // hh
#pragma unroll
            for (int ni = 0; ni < 4; ni++)
                mma16816(acc[mi][ni], ah, bl[ni]);   // hl
#pragma unroll
            for (int ni = 0; ni < 4; ni++)
                mma16816(acc[mi][ni], al, bh[ni]);   // lh
        }
    }
}

// ---------------------------------------------------------------------------
// Fused QKV projection GEMM. grid (8, 64, 3)
// ---------------------------------------------------------------------------
#define QSCALE 0.18033688011112042f   // 0.125 * log2(e): scores in log2 domain

__global__ void __launch_bounds__(256, 2) gemm_qkv_kernel(
    const float* __restrict__ bq, const float* __restrict__ bk,
    const float* __restrict__ bv)
{
    extern __shared__ char smem[];
    const uint32_t smem_u = smem_to_u32(smem);

    const int tid = threadIdx.x, wid = tid >> 5, lane = tid & 31;
    const int mtile = blockIdx.y, ntile = blockIdx.x, z = blockIdx.z;
    const int wm = wid & 1, wn = wid >> 1;

    const __nv_bfloat16* Bh_g = g_Wht + (size_t)z * DD * DD;
    const __nv_bfloat16* Bl_g = g_Wlt + (size_t)z * DD * DD;
    const float* bias = (z == 0) ? bq : (z == 1) ? bk : bv;
    __nv_bfloat16* Ch = (z == 0) ? g_Qh : (z == 1) ? g_Kh : g_Vh;
    __nv_bfloat16* Cl = (z == 0) ? g_Ql : (z == 1) ? g_Kl : g_Vl;
    const float scale = (z == 0) ? QSCALE : 1.0f;

    float acc[4][4][4];
#pragma unroll
    for (int mi = 0; mi < 4; mi++)
#pragma unroll
        for (int ni = 0; ni < 4; ni++)
#pragma unroll
            for (int r = 0; r < 4; r++) acc[mi][ni][r] = 0.0f;

    gemm_mainloop(smem_u, tid, lane, wm, wn,
                  g_Xh + (size_t)mtile * 128 * DD,
                  g_Xl + (size_t)mtile * 128 * DD,
                  Bh_g + (size_t)ntile * 128 * DD,
                  Bl_g + (size_t)ntile * 128 * DD, acc);

    const int mb = mtile * 128 + wm * 64 + (lane >> 2);
    const int nb0 = ntile * 128 + wn * 32 + (lane & 3) * 2;

#pragma unroll
    for (int mi = 0; mi < 4; mi++)
#pragma unroll
        for (int ni = 0; ni < 4; ni++) {
            int n = nb0 + ni * 8;
            float2 bsv = *(const float2*)(bias + n);
            int hh2 = n >> 6, hd = n & 63;
#pragma unroll
            for (int half = 0; half < 2; half++) {
                int mg = mb + mi * 16 + half * 8;
                float v0 = (acc[mi][ni][half * 2 + 0] + bsv.x) * scale;
                float v1 = (acc[mi][ni][half * 2 + 1] + bsv.y) * scale;
                __nv_bfloat162 hp = __floats2bfloat162_rn(v0, v1);
                __nv_bfloat162 lp = __floats2bfloat162_rn(
                    v0 - __bfloat162float(hp.x), v1 - __bfloat162float(hp.y));
                int bq2 = mg >> 12, sseq = mg & 4095;
                size_t off = ((size_t)(bq2 * HH + hh2) * SS + sseq) * HD + hd;
                *(__nv_bfloat162*)(Ch + off) = hp;
                *(__nv_bfloat162*)(Cl + off) = lp;
            }
        }
}

// ---------------------------------------------------------------------------
// Output projection GEMM. grid (8, 64)
// ---------------------------------------------------------------------------
__global__ void __launch_bounds__(256, 2) gemm_out_kernel(
    const float* __restrict__ bo, float* __restrict__ Cf)
{
    extern __shared__ char smem[];
    const uint32_t smem_u = smem_to_u32(smem);

    const int tid = threadIdx.x, wid = tid >> 5, lane = tid & 31;
    const int mtile = blockIdx.y, ntile = blockIdx.x;
    const int wm = wid & 1, wn = wid >> 1;

    float acc[4][4][4];
#pragma unroll
    for (int mi = 0; mi < 4; mi++)
#pragma unroll
        for (int ni = 0; ni < 4; ni++)
#pragma unroll
            for (int r = 0; r < 4; r++) acc[mi][ni][r] = 0.0f;

    gemm_mainloop(smem_u, tid, lane, wm, wn,
                  g_Ah + (size_t)mtile * 128 * DD,
                  g_Al + (size_t)mtile * 128 * DD,
                  g_Wht + 3 * (size_t)DD * DD + (size_t)ntile * 128 * DD,
                  g_Wlt + 3 * (size_t)DD * DD + (size_t)ntile * 128 * DD, acc);

    const int mb = mtile * 128 + wm * 64 + (lane >> 2);
    const int nb0 = ntile * 128 + wn * 32 + (lane & 3) * 2;

#pragma unroll
    for (int mi = 0; mi < 4; mi++)
#pragma unroll
        for (int ni = 0; ni < 4; ni++) {
            int n = nb0 + ni * 8;
            float2 bsv = *(const float2*)(bo + n);
#pragma unroll
            for (int half = 0; half < 2; half++) {
                int m = mb + mi * 16 + half * 8;
                float2 o;
                o.x = acc[mi][ni][half * 2 + 0] + bsv.x;
                o.y = acc[mi][ni][half * 2 + 1] + bsv.y;
                *(float2*)(Cf + (size_t)m * DD + n) = o;
            }
        }
}

// ---------------------------------------------------------------------------
// Flash attention, TQ=64, 128 threads, 3 CTAs/SM. (exact R10 winner)
// Fixed-shift softmax (m=0), deferred l reduction, inline exp+pack per j.
// ---------------------------------------------------------------------------
#define TQ 64
#define TK 64
#define QST 72
#define QTILE_B (64 * QST * 2)       // 9216
#define KTILE_B (64 * QST * 2)       // 9216
#define ATTN_SMEM (2 * 4 * KTILE_B)  // 73728
#define NT (SS / TK)

__global__ void __launch_bounds__(128, 3) attn_mma_kernel()
{
    extern __shared__ char smem[];
    const uint32_t smem_u = smem_to_u32(smem);
    const uint32_t sBuf = smem_u;

    const int tid = threadIdx.x, wid = tid >> 5, lane = tid & 31;
    const int b = blockIdx.z, h = blockIdx.y;
    const int q0 = blockIdx.x * TQ;
    const size_t bhoff = (size_t)(b * HH + h) * SS * HD;

    {
        const __nv_bfloat16* qsrc[2] = { g_Qh + bhoff + (size_t)q0 * HD,
                                         g_Ql + bhoff + (size_t)q0 * HD };
#pragma unroll
        for (int i = 0; i < 8; i++) {
            int seg = tid + i * 128;
            int arr = seg >> 9, rem = seg & 511;
            int row = rem >> 3, g = rem & 7;
            cp_async16(smem_u + (uint32_t)arr * QTILE_B + (uint32_t)(row * QST + g * 8) * 2,
                       qsrc[arr] + (size_t)row * HD + g * 8);
        }
    }
    CP_COMMIT();
    CP_WAIT0();
    __syncthreads();

    uint32_t qh[4][4], ql[4][4];
    {
        const int a_row = wid * 16 + (lane & 15);
        const int a_kof = (lane >> 4) * 8;
#pragma unroll
        for (int k = 0; k < 4; k++) {
            uint32_t ao = (uint32_t)(a_row * QST + k * 16 + a_kof) * 2;
            ldsm_x4(qh[k][0], qh[k][1], qh[k][2], qh[k][3], smem_u + ao);
            ldsm_x4(ql[k][0], ql[k][1], ql[k][2], ql[k][3], smem_u + QTILE_B + ao);
        }
    }
    __syncthreads();

    const __nv_bfloat16* kvsrc[4] = { g_Kh + bhoff, g_Kl + bhoff,
                                      g_Vh + bhoff, g_Vl + bhoff };
    auto issue_kv = [&](int t) {
        const uint32_t boff = sBuf + (uint32_t)(t & 1) * (4 * KTILE_B);
#pragma unroll
        for (int i = 0; i < 16; i++) {
            int seg = tid + i * 128;
            int arr = seg >> 9;
            int rem = seg & 511;
            int row = rem >> 3, g = rem & 7;
            cp_async16(boff + (uint32_t)arr * KTILE_B + (uint32_t)(row * QST + g * 8) * 2,
                       kvsrc[arr] + (size_t)(t * TK + row) * HD + g * 8);
        }
    };
    issue_kv(0); CP_COMMIT();

    float l0 = 0.0f, l1 = 0.0f;
    float o[8][4];
#pragma unroll
    for (int nb = 0; nb < 8; nb++)
#pragma unroll
        for (int r = 0; r < 4; r++) o[nb][r] = 0.0f;

    const int b_row = (lane & 7) + (lane >> 4) * 8;
    const int b_kof = ((lane >> 3) & 1) * 8;
    const int v_row = (lane & 15);
    const int v_col = (lane >> 4) * 8;

    for (int t = 0; t < NT; t++) {
        CP_WAIT0();
        __syncthreads();
        if (t < NT - 1) { issue_kv(t + 1); CP_COMMIT(); }

        const uint32_t boff = sBuf + (uint32_t)(t & 1) * (4 * KTILE_B);
        const uint32_t tKh = boff, tKl = boff + KTILE_B;
        const uint32_t tVh = boff + 2 * KTILE_B, tVl = boff + 3 * KTILE_B;

        float s[8][4];
#pragma unroll
        for (int nb = 0; nb < 8; nb++)
#pragma unroll
            for (int r = 0; r < 4; r++) s[nb][r] = 0.0f;

#pragma unroll
        for (int k = 0; k < 4; k++) {
            uint32_t kh[8][2], kl[8][2];
#pragma unroll
            for (int p = 0; p < 4; p++) {
                uint32_t bo = (uint32_t)((p * 16 + b_row) * QST + k * 16 + b_kof) * 2;
                ldsm_x4(kh[2 * p][0], kh[2 * p][1], kh[2 * p + 1][0], kh[2 * p + 1][1], tKh + bo);
                ldsm_x4(kl[2 * p][0], kl[2 * p][1], kl[2 * p + 1][0], kl[2 * p + 1][1], tKl + bo);
            }
#pragma unroll
            for (int nb = 0; nb < 8; nb++)
                mma16816(s[nb], qh[k], kh[nb]);   // hh
#pragma unroll
            for (int nb = 0; nb < 8; nb++)
                mma16816(s[nb], qh[k], kl[nb]);   // hl
#pragma unroll
            for (int nb = 0; nb < 8; nb++)
                mma16816(s[nb], ql[k], kh[nb]);   // lh
        }

#pragma unroll
        for (int j = 0; j < 4; j++) {
            float e00 = ex2(s[2 * j][0]),     e01 = ex2(s[2 * j][1]);
            float e02 = ex2(s[2 * j][2]),     e03 = ex2(s[2 * j][3]);
            float e10 = ex2(s[2 * j + 1][0]), e11 = ex2(s[2 * j + 1][1]);
            float e12 = ex2(s[2 * j + 1][2]), e13 = ex2(s[2 * j + 1][3]);
            l0 += e00 + e01 + e10 + e11;
            l1 += e02 + e03 + e12 + e13;

            uint32_t ph[4], pl[4];
            {
                float pv[4][2] = { {e00, e01}, {e02, e03}, {e10, e11}, {e12, e13} };
#pragma unroll
                for (int r = 0; r < 4; r++) {
                    __nv_bfloat162 hp = __floats2bfloat162_rn(pv[r][0], pv[r][1]);
                    __nv_bfloat162 lp = __floats2bfloat162_rn(
                        pv[r][0] - __bfloat162float(hp.x),
                        pv[r][1] - __bfloat162float(hp.y));
                    ph[r] = *reinterpret_cast<uint32_t*>(&hp);
                    pl[r] = *reinterpret_cast<uint32_t*>(&lp);
                }
            }
            uint32_t vh[8][2], vl[8][2];
#pragma unroll
            for (int p = 0; p < 4; p++) {
                uint32_t vo = (uint32_t)((j * 16 + v_row) * QST + p * 16 + v_col) * 2;
                ldsm_x4t(vh[2 * p][0], vh[2 * p][1], vh[2 * p + 1][0], vh[2 * p + 1][1], tVh + vo);
                ldsm_x4t(vl[2 * p][0], vl[2 * p][1], vl[2 * p + 1][0], vl[2 * p + 1][1], tVl + vo);
            }
#pragma unroll
            for (int nb = 0; nb < 8; nb++)
                mma16816(o[nb], ph, vh[nb]);   // hh
#pragma unroll
            for (int nb = 0; nb < 8; nb++)
                mma16816(o[nb], ph, vl[nb]);   // hl
#pragma unroll
            for (int nb = 0; nb < 8; nb++)
                mma16816(o[nb], pl, vh[nb]);   // lh
        }
    }

    l0 += __shfl_xor_sync(0xffffffffu, l0, 1);
    l0 += __shfl_xor_sync(0xffffffffu, l0, 2);
    l1 += __shfl_xor_sync(0xffffffffu, l1, 1);
    l1 += __shfl_xor_sync(0xffffffffu, l1, 2);
    const float inv0 = 1.0f / l0, inv1 = 1.0f / l1;

    const int qrow = q0 + wid * 16 + (lane >> 2);
    const size_t mrow0 = (size_t)(b * SS + qrow);
    const size_t mrow1 = mrow0 + 8;
    const int colb = h * HD + (lane & 3) * 2;
#pragma unroll
    for (int nb = 0; nb < 8; nb++) {
        int col = colb + nb * 8;
        float x0 = o[nb][0] * inv0, x1 = o[nb][1] * inv0;
        float x2 = o[nb][2] * inv1, x3 = o[nb][3] * inv1;
        __nv_bfloat162 h0 = __floats2bfloat162_rn(x0, x1);
        __nv_bfloat162 g0 = __floats2bfloat162_rn(
            x0 - __bfloat162float(h0.x), x1 - __bfloat162float(h0.y));
        __nv_bfloat162 h1 = __floats2bfloat162_rn(x2, x3);
        __nv_bfloat162 g1 = __floats2bfloat162_rn(
            x2 - __bfloat162float(h1.x), x3 - __bfloat162float(h1.y));
        *(__nv_bfloat162*)(g_Ah + mrow0 * DD + col) = h0;
        *(__nv_bfloat162*)(g_Al + mrow0 * DD + col) = g0;
        *(__nv_bfloat162*)(g_Ah + mrow1 * DD + col) = h1;
        *(__nv_bfloat162*)(g_Al + mrow1 * DD + col) = g1;
    }
}

// ---------------------------------------------------------------------------
// Launch
// ---------------------------------------------------------------------------
extern "C" void kernel_launch(void* const* d_in, const int* in_sizes, int n_in,
                              void* d_out, int out_size)
{
    (void)in_sizes; (void)n_in; (void)out_size;
    const float* X  = (const float*)d_in[0];
    const float* Wq = (const float*)d_in[1];
    const float* bq = (const float*)d_in[2];
    const float* Wk = (const float*)d_in[3];
    const float* bk = (const float*)d_in[4];
    const float* Wv = (const float*)d_in[5];
    const float* bv = (const float*)d_in[6];
    const float* Wo = (const float*)d_in[7];
    const float* bo = (const float*)d_in[8];
    float* out = (float*)d_out;

    __nv_bfloat16* pXh;
    __nv_bfloat16* pXl;
    cudaGetSymbolAddress((void**)&pXh, g_Xh);
    cudaGetSymbolAddress((void**)&pXl, g_Xl);

    cudaFuncSetAttribute(gemm_qkv_kernel,
                         cudaFuncAttributeMaxDynamicSharedMemorySize, GEMM_SMEM);
    cudaFuncSetAttribute(gemm_out_kernel,
                         cudaFuncAttributeMaxDynamicSharedMemorySize, GEMM_SMEM);
    cudaFuncSetAttribute(attn_mma_kernel,
                         cudaFuncAttributeMaxDynamicSharedMemorySize, ATTN_SMEM);

    xsplit_kernel<<<MM * DD / 4 / 256, 256>>>(X, pXh, pXl);
    dim3 gW(32, 32, 4), bW(32, 8);
    wsplit4_kernel<<<gW, bW>>>(Wq, Wk, Wv, Wo);

    dim3 gQKV(DD / 128, MM / 128, 3);   // (8, 64, 3)
    gemm_qkv_kernel<<<gQKV, 256, GEMM_SMEM>>>(bq, bk, bv);

    dim3 gattn(SS / TQ, HH, BB);        // (64, 16, 2)
    attn_mma_kernel<<<gattn, 128, ATTN_SMEM>>>();

    dim3 gO(DD / 128, MM / 128);        // (8, 64)
    gemm_out_kernel<<<gO, 256, GEMM_SMEM>>>(bo, out);
}

// round 15
// speedup vs baseline: 1.0465x; 1.0465x over previous
#include <cuda_runtime.h>
#include <cuda_bf16.h>
#include <cstdint>
#include <math.h>

// Problem constants
#define BB 2
#define SS 4096
#define DD 1024
#define HH 16
#define HD 64
#define MM (BB * SS)   // 8192

// ---------------------------------------------------------------------------
// Scratch (device globals)
// ---------------------------------------------------------------------------
__device__ __nv_bfloat16 g_Xh[MM * DD];
__device__ __nv_bfloat16 g_Xl[MM * DD];
__device__ __nv_bfloat16 g_Wht[4 * DD * DD];
__device__ __nv_bfloat16 g_Wlt[4 * DD * DD];
__device__ __nv_bfloat16 g_Qh[MM * DD];
__device__ __nv_bfloat16 g_Ql[MM * DD];
__device__ __nv_bfloat16 g_Kh[MM * DD];
__device__ __nv_bfloat16 g_Kl[MM * DD];
__device__ __nv_bfloat16 g_Vh[MM * DD];
__device__ __nv_bfloat16 g_Vl[MM * DD];
__device__ __nv_bfloat16 g_Ah[MM * DD];
__device__ __nv_bfloat16 g_Al[MM * DD];

// ---------------------------------------------------------------------------
// PTX helpers
// ---------------------------------------------------------------------------
__device__ __forceinline__ uint32_t smem_to_u32(const void* p) {
    uint32_t a;
    asm("{ .reg .u64 t; cvta.to.shared.u64 t, %1; cvt.u32.u64 %0, t; }"
        : "=r"(a) : "l"(p));
    return a;
}

__device__ __forceinline__ float ex2(float x) {
    float y;
    asm("ex2.approx.f32 %0, %1;" : "=f"(y) : "f"(x));
    return y;
}

__device__ __forceinline__ void cp_async16(uint32_t dst, const void* src) {
    asm volatile("cp.async.cg.shared.global [%0], [%1], 16;"
                 :: "r"(dst), "l"(src));
}
#define CP_COMMIT() asm volatile("cp.async.commit_group;" ::: "memory")
#define CP_WAIT0()  asm volatile("cp.async.wait_group 0;" ::: "memory")

__device__ __forceinline__ void ldsm_x4(uint32_t& r0, uint32_t& r1,
                                        uint32_t& r2, uint32_t& r3, uint32_t addr) {
    asm volatile("ldmatrix.sync.aligned.m8n8.x4.shared.b16 {%0,%1,%2,%3}, [%4];"
                 : "=r"(r0), "=r"(r1), "=r"(r2), "=r"(r3) : "r"(addr));
}

__device__ __forceinline__ void ldsm_x4t(uint32_t& r0, uint32_t& r1,
                                         uint32_t& r2, uint32_t& r3, uint32_t addr) {
    asm volatile("ldmatrix.sync.aligned.m8n8.x4.trans.shared.b16 {%0,%1,%2,%3}, [%4];"
                 : "=r"(r0), "=r"(r1), "=r"(r2), "=r"(r3) : "r"(addr));
}

__device__ __forceinline__ void mma16816(float* c, const uint32_t* a, const uint32_t* b) {
    asm volatile(
        "mma.sync.aligned.m16n8k16.row.col.f32.bf16.bf16.f32 "
        "{%0,%1,%2,%3}, {%4,%5,%6,%7}, {%8,%9}, {%0,%1,%2,%3};"
        : "+f"(c[0]), "+f"(c[1]), "+f"(c[2]), "+f"(c[3])
        : "r"(a[0]), "r"(a[1]), "r"(a[2]), "r"(a[3]), "r"(b[0]), "r"(b[1]));
}

// ---------------------------------------------------------------------------
// hi/lo bf16 split of X
// ---------------------------------------------------------------------------
__global__ void __launch_bounds__(256) xsplit_kernel(
    const float* __restrict__ X,
    __nv_bfloat16* __restrict__ Xh, __nv_bfloat16* __restrict__ Xl)
{
    int i = (blockIdx.x * 256 + threadIdx.x) * 4;
    float4 v = *(const float4*)(X + i);
    __nv_bfloat162 hp0 = __floats2bfloat162_rn(v.x, v.y);
    __nv_bfloat162 hp1 = __floats2bfloat162_rn(v.z, v.w);
    __nv_bfloat162 lp0 = __floats2bfloat162_rn(v.x - __bfloat162float(hp0.x),
                                               v.y - __bfloat162float(hp0.y));
    __nv_bfloat162 lp1 = __floats2bfloat162_rn(v.z - __bfloat162float(hp1.x),
                                               v.w - __bfloat162float(hp1.y));
    *(__nv_bfloat162*)(Xh + i)     = hp0;
    *(__nv_bfloat162*)(Xh + i + 2) = hp1;
    *(__nv_bfloat162*)(Xl + i)     = lp0;
    *(__nv_bfloat162*)(Xl + i + 2) = lp1;
}

// ---------------------------------------------------------------------------
// Transpose + split all 4 weights
// ---------------------------------------------------------------------------
__global__ void __launch_bounds__(256) wsplit4_kernel(
    const float* __restrict__ W0, const float* __restrict__ W1,
    const float* __restrict__ W2, const float* __restrict__ W3)
{
    __shared__ float t[32][33];
    const int z = blockIdx.z;
    const float* W = (z == 0) ? W0 : (z == 1) ? W1 : (z == 2) ? W2 : W3;
    __nv_bfloat16* Wht = g_Wht + (size_t)z * DD * DD;
    __nv_bfloat16* Wlt = g_Wlt + (size_t)z * DD * DD;

    int tx = threadIdx.x, ty = threadIdx.y;
    int n0 = blockIdx.x * 32, k0 = blockIdx.y * 32;
#pragma unroll
    for (int i = 0; i < 4; i++)
        t[ty + i * 8][tx] = W[(size_t)(k0 + ty + i * 8) * DD + n0 + tx];
    __syncthreads();
#pragma unroll
    for (int i = 0; i < 4; i++) {
        float v = t[tx][ty + i * 8];
        __nv_bfloat16 h = __float2bfloat16_rn(v);
        __nv_bfloat16 l = __float2bfloat16_rn(v - __bfloat162float(h));
        size_t idx = (size_t)(n0 + ty + i * 8) * DD + k0 + tx;
        Wht[idx] = h;
        Wlt[idx] = l;
    }
}

// ---------------------------------------------------------------------------
// GEMM mainloop (R10 champion: 64x128 CTA tile, 128 threads, KC=32,
//   double-buffered, 3 CTAs/SM)
// ---------------------------------------------------------------------------
#define KC 32
#define GSTRIDE 40
#define TILE_A (64 * GSTRIDE * 2)
#define TILE_BB (128 * GSTRIDE * 2)
#define BUF_B  (2 * TILE_A + 2 * TILE_BB)
#define GEMM_SMEM (2 * BUF_B)            // 61440

__device__ __forceinline__ void gemm_mainloop(
    uint32_t smem_u, int tid, int lane, int wm, int wn,
    const __nv_bfloat16* ah_g, const __nv_bfloat16* al_g,
    const __nv_bfloat16* bh_g, const __nv_bfloat16* bl_g,
    float acc[2][8][4])
{
    auto issue_chunk = [&](int c) {
        const uint32_t boff = smem_u + (uint32_t)(c & 1) * BUF_B;
#pragma unroll
        for (int i = 0; i < 4; i++) {
            int seg = tid + i * 128;
            int t = seg >> 8;
            int rem = seg & 255;
            int row = rem >> 2, g = rem & 3;
            const __nv_bfloat16* src = t ? al_g : ah_g;
            cp_async16(boff + (uint32_t)t * TILE_A
                       + (uint32_t)(row * GSTRIDE + g * 8) * 2,
                       src + (size_t)row * DD + c * KC + g * 8);
        }
#pragma unroll
        for (int i = 0; i < 8; i++) {
            int seg = tid + i * 128;
            int t = seg >> 9;
            int rem = seg & 511;
            int row = rem >> 2, g = rem & 3;
            const __nv_bfloat16* src = t ? bl_g : bh_g;
            cp_async16(boff + 2 * TILE_A + (uint32_t)t * TILE_BB
                       + (uint32_t)(row * GSTRIDE + g * 8) * 2,
                       src + (size_t)row * DD + c * KC + g * 8);
        }
    };

    const int a_row = wm * 32 + (lane & 15);
    const int a_kof = (lane >> 4) * 8;
    const int b_row = wn * 64 + (lane & 7) + (lane >> 4) * 8;
    const int b_kof = ((lane >> 3) & 1) * 8;

    issue_chunk(0);
    CP_COMMIT();

    for (int c = 0; c < 32; c++) {
        CP_WAIT0();
        __syncthreads();
        if (c < 31) { issue_chunk(c + 1); CP_COMMIT(); }

        const uint32_t boff = smem_u + (uint32_t)(c & 1) * BUF_B;
        const uint32_t tAh = boff;
        const uint32_t tAl = boff + TILE_A;
        const uint32_t tBh = boff + 2 * TILE_A;
        const uint32_t tBl = boff + 2 * TILE_A + TILE_BB;

#pragma unroll
        for (int kb = 0; kb < KC; kb += 16) {
            uint32_t ah[2][4], al[2][4], bh[8][2], bl[8][2];
#pragma unroll
            for (int mi = 0; mi < 2; mi++) {
                uint32_t ao = (uint32_t)((a_row + mi * 16) * GSTRIDE + kb + a_kof) * 2;
                ldsm_x4(ah[mi][0], ah[mi][1], ah[mi][2], ah[mi][3], tAh + ao);
                ldsm_x4(al[mi][0], al[mi][1], al[mi][2], al[mi][3], tAl + ao);
            }
#pragma unroll
            for (int p = 0; p < 4; p++) {
                uint32_t bo = (uint32_t)((p * 16 + b_row) * GSTRIDE + kb + b_kof) * 2;
                ldsm_x4(bh[2 * p][0], bh[2 * p][1], bh[2 * p + 1][0], bh[2 * p + 1][1], tBh + bo);
                ldsm_x4(bl[2 * p][0], bl[2 * p][1], bl[2 * p + 1][0], bl[2 * p + 1][1], tBl + bo);
            }
#pragma unroll
            for (int mi = 0; mi < 2; mi++)
#pragma unroll
                for (int ni = 0; ni < 8; ni++)
                    mma16816(acc[mi][ni], ah[mi], bh[ni]);   // hh
#pragma unroll
            for (int mi = 0; mi < 2; mi++)
#pragma unroll
                for (int ni = 0; ni < 8; ni++)
                    mma16816(acc[mi][ni], ah[mi], bl[ni]);   // hl
#pragma unroll
            for (int mi = 0; mi < 2; mi++)
#pragma unroll
                for (int ni = 0; ni < 8; ni++)
                    mma16816(acc[mi][ni], al[mi], bh[ni]);   // lh
        }
        __syncthreads();
    }
}

// ---------------------------------------------------------------------------
// Fused QKV projection GEMM. grid (8, 128, 3)
// ---------------------------------------------------------------------------
#define QSCALE 0.18033688011112042f   // 0.125 * log2(e): scores in log2 domain

__global__ void __launch_bounds__(128, 3) gemm_qkv_kernel(
    const float* __restrict__ bq, const float* __restrict__ bk,
    const float* __restrict__ bv)
{
    extern __shared__ char smem[];
    const uint32_t smem_u = smem_to_u32(smem);

    const int tid = threadIdx.x, wid = tid >> 5, lane = tid & 31;
    const int mtile = blockIdx.y, ntile = blockIdx.x, z = blockIdx.z;
    const int wm = wid & 1, wn = wid >> 1;

    const __nv_bfloat16* Bh_g = g_Wht + (size_t)z * DD * DD;
    const __nv_bfloat16* Bl_g = g_Wlt + (size_t)z * DD * DD;
    const float* bias = (z == 0) ? bq : (z == 1) ? bk : bv;
    __nv_bfloat16* Ch = (z == 0) ? g_Qh : (z == 1) ? g_Kh : g_Vh;
    __nv_bfloat16* Cl = (z == 0) ? g_Ql : (z == 1) ? g_Kl : g_Vl;
    const float scale = (z == 0) ? QSCALE : 1.0f;

    float acc[2][8][4];
#pragma unroll
    for (int mi = 0; mi < 2; mi++)
#pragma unroll
        for (int ni = 0; ni < 8; ni++)
#pragma unroll
            for (int r = 0; r < 4; r++) acc[mi][ni][r] = 0.0f;

    gemm_mainloop(smem_u, tid, lane, wm, wn,
                  g_Xh + (size_t)mtile * 64 * DD,
                  g_Xl + (size_t)mtile * 64 * DD,
                  Bh_g + (size_t)ntile * 128 * DD,
                  Bl_g + (size_t)ntile * 128 * DD, acc);

    const int mb = mtile * 64 + wm * 32 + (lane >> 2);
    const int nb0 = ntile * 128 + wn * 64 + (lane & 3) * 2;

#pragma unroll
    for (int mi = 0; mi < 2; mi++)
#pragma unroll
        for (int ni = 0; ni < 8; ni++) {
            int n = nb0 + ni * 8;
            float2 bsv = *(const float2*)(bias + n);
            int hh2 = n >> 6, hd = n & 63;
#pragma unroll
            for (int half = 0; half < 2; half++) {
                int mg = mb + mi * 16 + half * 8;
                float v0 = (acc[mi][ni][half * 2 + 0] + bsv.x) * scale;
                float v1 = (acc[mi][ni][half * 2 + 1] + bsv.y) * scale;
                __nv_bfloat162 hp = __floats2bfloat162_rn(v0, v1);
                __nv_bfloat162 lp = __floats2bfloat162_rn(
                    v0 - __bfloat162float(hp.x), v1 - __bfloat162float(hp.y));
                int bq2 = mg >> 12, sseq = mg & 4095;
                size_t off = ((size_t)(bq2 * HH + hh2) * SS + sseq) * HD + hd;
                *(__nv_bfloat162*)(Ch + off) = hp;
                *(__nv_bfloat162*)(Cl + off) = lp;
            }
        }
}

// ---------------------------------------------------------------------------
// Output projection GEMM. grid (8, 128)
// ---------------------------------------------------------------------------
__global__ void __launch_bounds__(128, 3) gemm_out_kernel(
    const float* __restrict__ bo, float* __restrict__ Cf)
{
    extern __shared__ char smem[];
    const uint32_t smem_u = smem_to_u32(smem);

    const int tid = threadIdx.x, wid = tid >> 5, lane = tid & 31;
    const int mtile = blockIdx.y, ntile = blockIdx.x;
    const int wm = wid & 1, wn = wid >> 1;

    float acc[2][8][4];
#pragma unroll
    for (int mi = 0; mi < 2; mi++)
#pragma unroll
        for (int ni = 0; ni < 8; ni++)
#pragma unroll
            for (int r = 0; r < 4; r++) acc[mi][ni][r] = 0.0f;

    gemm_mainloop(smem_u, tid, lane, wm, wn,
                  g_Ah + (size_t)mtile * 64 * DD,
                  g_Al + (size_t)mtile * 64 * DD,
                  g_Wht + 3 * (size_t)DD * DD + (size_t)ntile * 128 * DD,
                  g_Wlt + 3 * (size_t)DD * DD + (size_t)ntile * 128 * DD, acc);

    const int mb = mtile * 64 + wm * 32 + (lane >> 2);
    const int nb0 = ntile * 128 + wn * 64 + (lane & 3) * 2;

#pragma unroll
    for (int mi = 0; mi < 2; mi++)
#pragma unroll
        for (int ni = 0; ni < 8; ni++) {
            int n = nb0 + ni * 8;
            float2 bsv = *(const float2*)(bo + n);
#pragma unroll
            for (int half = 0; half < 2; half++) {
                int m = mb + mi * 16 + half * 8;
                float2 o;
                o.x = acc[mi][ni][half * 2 + 0] + bsv.x;
                o.y = acc[mi][ni][half * 2 + 1] + bsv.y;
                *(float2*)(Cf + (size_t)m * DD + n) = o;
            }
        }
}

// ---------------------------------------------------------------------------
// Flash attention, TQ=64, 128 threads, 3 CTAs/SM (R10 winner) + CTA
// de-phasing: each CTA starts its KV sweep at a rotated tile offset so
// co-resident CTAs hit softmax at different times (valid because fixed-shift
// softmax is tile-order commutative).
// ---------------------------------------------------------------------------
#define TQ 64
#define TK 64
#define QST 72
#define QTILE_B (64 * QST * 2)       // 9216
#define KTILE_B (64 * QST * 2)       // 9216
#define ATTN_SMEM (2 * 4 * KTILE_B)  // 73728
#define NT (SS / TK)

__global__ void __launch_bounds__(128, 3) attn_mma_kernel()
{
    extern __shared__ char smem[];
    const uint32_t smem_u = smem_to_u32(smem);
    const uint32_t sBuf = smem_u;

    const int tid = threadIdx.x, wid = tid >> 5, lane = tid & 31;
    const int b = blockIdx.z, h = blockIdx.y;
    const int q0 = blockIdx.x * TQ;
    const size_t bhoff = (size_t)(b * HH + h) * SS * HD;

    // De-phase: wave index mod 3 -> tile rotation (co-resident CTAs differ)
    const int bid = blockIdx.x + 64 * (blockIdx.y + 16 * blockIdx.z);
    const int t0 = ((bid / 148) % 3) * 21;

    {
        const __nv_bfloat16* qsrc[2] = { g_Qh + bhoff + (size_t)q0 * HD,
                                         g_Ql + bhoff + (size_t)q0 * HD };
#pragma unroll
        for (int i = 0; i < 8; i++) {
            int seg = tid + i * 128;
            int arr = seg >> 9, rem = seg & 511;
            int row = rem >> 3, g = rem & 7;
            cp_async16(smem_u + (uint32_t)arr * QTILE_B + (uint32_t)(row * QST + g * 8) * 2,
                       qsrc[arr] + (size_t)row * HD + g * 8);
        }
    }
    CP_COMMIT();
    CP_WAIT0();
    __syncthreads();

    uint32_t qh[4][4], ql[4][4];
    {
        const int a_row = wid * 16 + (lane & 15);
        const int a_kof = (lane >> 4) * 8;
#pragma unroll
        for (int k = 0; k < 4; k++) {
            uint32_t ao = (uint32_t)(a_row * QST + k * 16 + a_kof) * 2;
            ldsm_x4(qh[k][0], qh[k][1], qh[k][2], qh[k][3], smem_u + ao);
            ldsm_x4(ql[k][0], ql[k][1], ql[k][2], ql[k][3], smem_u + QTILE_B + ao);
        }
    }
    __syncthreads();

    const __nv_bfloat16* kvsrc[4] = { g_Kh + bhoff, g_Kl + bhoff,
                                      g_Vh + bhoff, g_Vl + bhoff };
    // Stage tile `tile` into ring buffer `buf` (buffer keyed by iteration).
    auto issue_kv = [&](int tile, int buf) {
        const uint32_t boff = sBuf + (uint32_t)buf * (4 * KTILE_B);
#pragma unroll
        for (int i = 0; i < 16; i++) {
            int seg = tid + i * 128;
            int arr = seg >> 9;
            int rem = seg & 511;
            int row = rem >> 3, g = rem & 7;
            cp_async16(boff + (uint32_t)arr * KTILE_B + (uint32_t)(row * QST + g * 8) * 2,
                       kvsrc[arr] + (size_t)(tile * TK + row) * HD + g * 8);
        }
    };
    issue_kv(t0, 0); CP_COMMIT();

    float l0 = 0.0f, l1 = 0.0f;
    float o[8][4];
#pragma unroll
    for (int nb = 0; nb < 8; nb++)
#pragma unroll
        for (int r = 0; r < 4; r++) o[nb][r] = 0.0f;

    const int b_row = (lane & 7) + (lane >> 4) * 8;
    const int b_kof = ((lane >> 3) & 1) * 8;
    const int v_row = (lane & 15);
    const int v_col = (lane >> 4) * 8;

    for (int t = 0; t < NT; t++) {
        CP_WAIT0();
        __syncthreads();
        if (t < NT - 1) {
            int tn = t0 + t + 1; if (tn >= NT) tn -= NT;
            issue_kv(tn, (t + 1) & 1); CP_COMMIT();
        }

        const uint32_t boff = sBuf + (uint32_t)(t & 1) * (4 * KTILE_B);
        const uint32_t tKh = boff, tKl = boff + KTILE_B;
        const uint32_t tVh = boff + 2 * KTILE_B, tVl = boff + 3 * KTILE_B;

        float s[8][4];
#pragma unroll
        for (int nb = 0; nb < 8; nb++)
#pragma unroll
            for (int r = 0; r < 4; r++) s[nb][r] = 0.0f;

#pragma unroll
        for (int k = 0; k < 4; k++) {
            uint32_t kh[8][2], kl[8][2];
#pragma unroll
            for (int p = 0; p < 4; p++) {
                uint32_t bo = (uint32_t)((p * 16 + b_row) * QST + k * 16 + b_kof) * 2;
                ldsm_x4(kh[2 * p][0], kh[2 * p][1], kh[2 * p + 1][0], kh[2 * p + 1][1], tKh + bo);
                ldsm_x4(kl[2 * p][0], kl[2 * p][1], kl[2 * p + 1][0], kl[2 * p + 1][1], tKl + bo);
            }
#pragma unroll
            for (int nb = 0; nb < 8; nb++)
                mma16816(s[nb], qh[k], kh[nb]);   // hh
#pragma unroll
            for (int nb = 0; nb < 8; nb++)
                mma16816(s[nb], qh[k], kl[nb]);   // hl
#pragma unroll
            for (int nb = 0; nb < 8; nb++)
                mma16816(s[nb], ql[k], kh[nb]);   // lh
        }

#pragma unroll
        for (int j = 0; j < 4; j++) {
            float e00 = ex2(s[2 * j][0]),     e01 = ex2(s[2 * j][1]);
            float e02 = ex2(s[2 * j][2]),     e03 = ex2(s[2 * j][3]);
            float e10 = ex2(s[2 * j + 1][0]), e11 = ex2(s[2 * j + 1][1]);
            float e12 = ex2(s[2 * j + 1][2]), e13 = ex2(s[2 * j + 1][3]);
            l0 += e00 + e01 + e10 + e11;
            l1 += e02 + e03 + e12 + e13;

            uint32_t ph[4], pl[4];
            {
                float pv[4][2] = { {e00, e01}, {e02, e03}, {e10, e11}, {e12, e13} };
#pragma unroll
                for (int r = 0; r < 4; r++) {
                    __nv_bfloat162 hp = __floats2bfloat162_rn(pv[r][0], pv[r][1]);
                    __nv_bfloat162 lp = __floats2bfloat162_rn(
                        pv[r][0] - __bfloat162float(hp.x),
                        pv[r][1] - __bfloat162float(hp.y));
                    ph[r] = *reinterpret_cast<uint32_t*>(&hp);
                    pl[r] = *reinterpret_cast<uint32_t*>(&lp);
                }
            }
            uint32_t vh[8][2], vl[8][2];
#pragma unroll
            for (int p = 0; p < 4; p++) {
                uint32_t vo = (uint32_t)((j * 16 + v_row) * QST + p * 16 + v_col) * 2;
                ldsm_x4t(vh[2 * p][0], vh[2 * p][1], vh[2 * p + 1][0], vh[2 * p + 1][1], tVh + vo);
                ldsm_x4t(vl[2 * p][0], vl[2 * p][1], vl[2 * p + 1][0], vl[2 * p + 1][1], tVl + vo);
            }
#pragma unroll
            for (int nb = 0; nb < 8; nb++)
                mma16816(o[nb], ph, vh[nb]);   // hh
#pragma unroll
            for (int nb = 0; nb < 8; nb++)
                mma16816(o[nb], ph, vl[nb]);   // hl
#pragma unroll
            for (int nb = 0; nb < 8; nb++)
                mma16816(o[nb], pl, vh[nb]);   // lh
        }
    }

    l0 += __shfl_xor_sync(0xffffffffu, l0, 1);
    l0 += __shfl_xor_sync(0xffffffffu, l0, 2);
    l1 += __shfl_xor_sync(0xffffffffu, l1, 1);
    l1 += __shfl_xor_sync(0xffffffffu, l1, 2);
    const float inv0 = 1.0f / l0, inv1 = 1.0f / l1;

    const int qrow = q0 + wid * 16 + (lane >> 2);
    const size_t mrow0 = (size_t)(b * SS + qrow);
    const size_t mrow1 = mrow0 + 8;
    const int colb = h * HD + (lane & 3) * 2;
#pragma unroll
    for (int nb = 0; nb < 8; nb++) {
        int col = colb + nb * 8;
        float x0 = o[nb][0] * inv0, x1 = o[nb][1] * inv0;
        float x2 = o[nb][2] * inv1, x3 = o[nb][3] * inv1;
        __nv_bfloat162 h0 = __floats2bfloat162_rn(x0, x1);
        __nv_bfloat162 g0 = __floats2bfloat162_rn(
            x0 - __bfloat162float(h0.x), x1 - __bfloat162float(h0.y));
        __nv_bfloat162 h1 = __floats2bfloat162_rn(x2, x3);
        __nv_bfloat162 g1 = __floats2bfloat162_rn(
            x2 - __bfloat162float(h1.x), x3 - __bfloat162float(h1.y));
        *(__nv_bfloat162*)(g_Ah + mrow0 * DD + col) = h0;
        *(__nv_bfloat162*)(g_Al + mrow0 * DD + col) = g0;
        *(__nv_bfloat162*)(g_Ah + mrow1 * DD + col) = h1;
        *(__nv_bfloat162*)(g_Al + mrow1 * DD + col) = g1;
    }
}

// ---------------------------------------------------------------------------
// Launch
// ---------------------------------------------------------------------------
extern "C" void kernel_launch(void* const* d_in, const int* in_sizes, int n_in,
                              void* d_out, int out_size)
{
    (void)in_sizes; (void)n_in; (void)out_size;
    const float* X  = (const float*)d_in[0];
    const float* Wq = (const float*)d_in[1];
    const float* bq = (const float*)d_in[2];
    const float* Wk = (const float*)d_in[3];
    const float* bk = (const float*)d_in[4];
    const float* Wv = (const float*)d_in[5];
    const float* bv = (const float*)d_in[6];
    const float* Wo = (const float*)d_in[7];
    const float* bo = (const float*)d_in[8];
    float* out = (float*)d_out;

    __nv_bfloat16* pXh;
    __nv_bfloat16* pXl;
    cudaGetSymbolAddress((void**)&pXh, g_Xh);
    cudaGetSymbolAddress((void**)&pXl, g_Xl);

    cudaFuncSetAttribute(gemm_qkv_kernel,
                         cudaFuncAttributeMaxDynamicSharedMemorySize, GEMM_SMEM);
    cudaFuncSetAttribute(gemm_out_kernel,
                         cudaFuncAttributeMaxDynamicSharedMemorySize, GEMM_SMEM);
    cudaFuncSetAttribute(attn_mma_kernel,
                         cudaFuncAttributeMaxDynamicSharedMemorySize, ATTN_SMEM);

    xsplit_kernel<<<MM * DD / 4 / 256, 256>>>(X, pXh, pXl);
    dim3 gW(32, 32, 4), bW(32, 8);
    wsplit4_kernel<<<gW, bW>>>(Wq, Wk, Wv, Wo);

    dim3 gQKV(DD / 128, MM / 64, 3);    // (8, 128, 3)
    gemm_qkv_kernel<<<gQKV, 128, GEMM_SMEM>>>(bq, bk, bv);

    dim3 gattn(SS / TQ, HH, BB);        // (64, 16, 2)
    attn_mma_kernel<<<gattn, 128, ATTN_SMEM>>>();

    dim3 gO(DD / 128, MM / 64);         // (8, 128)
    gemm_out_kernel<<<gO, 128, GEMM_SMEM>>>(bo, out);
}

// round 16
// speedup vs baseline: 1.0914x; 1.0429x over previous
#include <cuda_runtime.h>
#include <cuda_bf16.h>
#include <cstdint>
#include <math.h>

// Problem constants
#define BB 2
#define SS 4096
#define DD 1024
#define HH 16
#define HD 64
#define MM (BB * SS)   // 8192

// ---------------------------------------------------------------------------
// Scratch (device globals)
// ---------------------------------------------------------------------------
__device__ __nv_bfloat16 g_Xh[MM * DD];
__device__ __nv_bfloat16 g_Xl[MM * DD];
__device__ __nv_bfloat16 g_Wht[4 * DD * DD];
__device__ __nv_bfloat16 g_Wlt[4 * DD * DD];
__device__ __nv_bfloat16 g_Qh[MM * DD];
__device__ __nv_bfloat16 g_Ql[MM * DD];
__device__ __nv_bfloat16 g_Kh[MM * DD];
__device__ __nv_bfloat16 g_Kl[MM * DD];
__device__ __nv_bfloat16 g_Vh[MM * DD];
__device__ __nv_bfloat16 g_Vl[MM * DD];
__device__ __nv_bfloat16 g_Ah[MM * DD];
__device__ __nv_bfloat16 g_Al[MM * DD];

// ---------------------------------------------------------------------------
// PTX helpers
// ---------------------------------------------------------------------------
__device__ __forceinline__ uint32_t smem_to_u32(const void* p) {
    uint32_t a;
    asm("{ .reg .u64 t; cvta.to.shared.u64 t, %1; cvt.u32.u64 %0, t; }"
        : "=r"(a) : "l"(p));
    return a;
}

__device__ __forceinline__ float ex2(float x) {
    float y;
    asm("ex2.approx.f32 %0, %1;" : "=f"(y) : "f"(x));
    return y;
}

__device__ __forceinline__ void cp_async16(uint32_t dst, const void* src) {
    asm volatile("cp.async.cg.shared.global [%0], [%1], 16;"
                 :: "r"(dst), "l"(src));
}
#define CP_COMMIT() asm volatile("cp.async.commit_group;" ::: "memory")
#define CP_WAIT1()  asm volatile("cp.async.wait_group 1;" ::: "memory")
#define CP_WAIT0()  asm volatile("cp.async.wait_group 0;" ::: "memory")

__device__ __forceinline__ void ldsm_x4(uint32_t& r0, uint32_t& r1,
                                        uint32_t& r2, uint32_t& r3, uint32_t addr) {
    asm volatile("ldmatrix.sync.aligned.m8n8.x4.shared.b16 {%0,%1,%2,%3}, [%4];"
                 : "=r"(r0), "=r"(r1), "=r"(r2), "=r"(r3) : "r"(addr));
}

__device__ __forceinline__ void ldsm_x4t(uint32_t& r0, uint32_t& r1,
                                         uint32_t& r2, uint32_t& r3, uint32_t addr) {
    asm volatile("ldmatrix.sync.aligned.m8n8.x4.trans.shared.b16 {%0,%1,%2,%3}, [%4];"
                 : "=r"(r0), "=r"(r1), "=r"(r2), "=r"(r3) : "r"(addr));
}

__device__ __forceinline__ void mma16816(float* c, const uint32_t* a, const uint32_t* b) {
    asm volatile(
        "mma.sync.aligned.m16n8k16.row.col.f32.bf16.bf16.f32 "
        "{%0,%1,%2,%3}, {%4,%5,%6,%7}, {%8,%9}, {%0,%1,%2,%3};"
        : "+f"(c[0]), "+f"(c[1]), "+f"(c[2]), "+f"(c[3])
        : "r"(a[0]), "r"(a[1]), "r"(a[2]), "r"(a[3]), "r"(b[0]), "r"(b[1]));
}

// ---------------------------------------------------------------------------
// hi/lo bf16 split of X
// ---------------------------------------------------------------------------
__global__ void __launch_bounds__(256) xsplit_kernel(
    const float* __restrict__ X,
    __nv_bfloat16* __restrict__ Xh, __nv_bfloat16* __restrict__ Xl)
{
    int i = (blockIdx.x * 256 + threadIdx.x) * 4;
    float4 v = *(const float4*)(X + i);
    __nv_bfloat162 hp0 = __floats2bfloat162_rn(v.x, v.y);
    __nv_bfloat162 hp1 = __floats2bfloat162_rn(v.z, v.w);
    __nv_bfloat162 lp0 = __floats2bfloat162_rn(v.x - __bfloat162float(hp0.x),
                                               v.y - __bfloat162float(hp0.y));
    __nv_bfloat162 lp1 = __floats2bfloat162_rn(v.z - __bfloat162float(hp1.x),
                                               v.w - __bfloat162float(hp1.y));
    *(__nv_bfloat162*)(Xh + i)     = hp0;
    *(__nv_bfloat162*)(Xh + i + 2) = hp1;
    *(__nv_bfloat162*)(Xl + i)     = lp0;
    *(__nv_bfloat162*)(Xl + i + 2) = lp1;
}

// ---------------------------------------------------------------------------
// Transpose + split all 4 weights
// ---------------------------------------------------------------------------
__global__ void __launch_bounds__(256) wsplit4_kernel(
    const float* __restrict__ W0, const float* __restrict__ W1,
    const float* __restrict__ W2, const float* __restrict__ W3)
{
    __shared__ float t[32][33];
    const int z = blockIdx.z;
    const float* W = (z == 0) ? W0 : (z == 1) ? W1 : (z == 2) ? W2 : W3;
    __nv_bfloat16* Wht = g_Wht + (size_t)z * DD * DD;
    __nv_bfloat16* Wlt = g_Wlt + (size_t)z * DD * DD;

    int tx = threadIdx.x, ty = threadIdx.y;
    int n0 = blockIdx.x * 32, k0 = blockIdx.y * 32;
#pragma unroll
    for (int i = 0; i < 4; i++)
        t[ty + i * 8][tx] = W[(size_t)(k0 + ty + i * 8) * DD + n0 + tx];
    __syncthreads();
#pragma unroll
    for (int i = 0; i < 4; i++) {
        float v = t[tx][ty + i * 8];
        __nv_bfloat16 h = __float2bfloat16_rn(v);
        __nv_bfloat16 l = __float2bfloat16_rn(v - __bfloat162float(h));
        size_t idx = (size_t)(n0 + ty + i * 8) * DD + k0 + tx;
        Wht[idx] = h;
        Wlt[idx] = l;
    }
}

// ---------------------------------------------------------------------------
// GEMM mainloop (R10 champion: 64x128 CTA tile, 128 threads, KC=32,
//   double-buffered, 3 CTAs/SM). Single barrier per chunk: the top-of-loop
//   wait+sync of iter c already orders iter c-1's reads of buf[(c+1)&1]
//   before this iter's issue overwrites it.
// ---------------------------------------------------------------------------
#define KC 32
#define GSTRIDE 40
#define TILE_A (64 * GSTRIDE * 2)
#define TILE_BB (128 * GSTRIDE * 2)
#define BUF_B  (2 * TILE_A + 2 * TILE_BB)
#define GEMM_SMEM (2 * BUF_B)            // 61440

__device__ __forceinline__ void gemm_mainloop(
    uint32_t smem_u, int tid, int lane, int wm, int wn,
    const __nv_bfloat16* ah_g, const __nv_bfloat16* al_g,
    const __nv_bfloat16* bh_g, const __nv_bfloat16* bl_g,
    float acc[2][8][4])
{
    auto issue_chunk = [&](int c) {
        const uint32_t boff = smem_u + (uint32_t)(c & 1) * BUF_B;
#pragma unroll
        for (int i = 0; i < 4; i++) {
            int seg = tid + i * 128;
            int t = seg >> 8;
            int rem = seg & 255;
            int row = rem >> 2, g = rem & 3;
            const __nv_bfloat16* src = t ? al_g : ah_g;
            cp_async16(boff + (uint32_t)t * TILE_A
                       + (uint32_t)(row * GSTRIDE + g * 8) * 2,
                       src + (size_t)row * DD + c * KC + g * 8);
        }
#pragma unroll
        for (int i = 0; i < 8; i++) {
            int seg = tid + i * 128;
            int t = seg >> 9;
            int rem = seg & 511;
            int row = rem >> 2, g = rem & 3;
            const __nv_bfloat16* src = t ? bl_g : bh_g;
            cp_async16(boff + 2 * TILE_A + (uint32_t)t * TILE_BB
                       + (uint32_t)(row * GSTRIDE + g * 8) * 2,
                       src + (size_t)row * DD + c * KC + g * 8);
        }
    };

    const int a_row = wm * 32 + (lane & 15);
    const int a_kof = (lane >> 4) * 8;
    const int b_row = wn * 64 + (lane & 7) + (lane >> 4) * 8;
    const int b_kof = ((lane >> 3) & 1) * 8;

    issue_chunk(0);
    CP_COMMIT();

    for (int c = 0; c < 32; c++) {
        CP_WAIT0();
        __syncthreads();                 // chunk c visible; iter c-1 reads done
        if (c < 31) { issue_chunk(c + 1); CP_COMMIT(); }

        const uint32_t boff = smem_u + (uint32_t)(c & 1) * BUF_B;
        const uint32_t tAh = boff;
        const uint32_t tAl = boff + TILE_A;
        const uint32_t tBh = boff + 2 * TILE_A;
        const uint32_t tBl = boff + 2 * TILE_A + TILE_BB;

#pragma unroll
        for (int kb = 0; kb < KC; kb += 16) {
            uint32_t ah[2][4], al[2][4], bh[8][2], bl[8][2];
#pragma unroll
            for (int mi = 0; mi < 2; mi++) {
                uint32_t ao = (uint32_t)((a_row + mi * 16) * GSTRIDE + kb + a_kof) * 2;
                ldsm_x4(ah[mi][0], ah[mi][1], ah[mi][2], ah[mi][3], tAh + ao);
                ldsm_x4(al[mi][0], al[mi][1], al[mi][2], al[mi][3], tAl + ao);
            }
#pragma unroll
            for (int p = 0; p < 4; p++) {
                uint32_t bo = (uint32_t)((p * 16 + b_row) * GSTRIDE + kb + b_kof) * 2;
                ldsm_x4(bh[2 * p][0], bh[2 * p][1], bh[2 * p + 1][0], bh[2 * p + 1][1], tBh + bo);
                ldsm_x4(bl[2 * p][0], bl[2 * p][1], bl[2 * p + 1][0], bl[2 * p + 1][1], tBl + bo);
            }
#pragma unroll
            for (int mi = 0; mi < 2; mi++)
#pragma unroll
                for (int ni = 0; ni < 8; ni++)
                    mma16816(acc[mi][ni], ah[mi], bh[ni]);   // hh
#pragma unroll
            for (int mi = 0; mi < 2; mi++)
#pragma unroll
                for (int ni = 0; ni < 8; ni++)
                    mma16816(acc[mi][ni], ah[mi], bl[ni]);   // hl
#pragma unroll
            for (int mi = 0; mi < 2; mi++)
#pragma unroll
                for (int ni = 0; ni < 8; ni++)
                    mma16816(acc[mi][ni], al[mi], bh[ni]);   // lh
        }
    }
}

// ---------------------------------------------------------------------------
// Fused QKV projection GEMM. grid (8, 128, 3)
// ---------------------------------------------------------------------------
#define QSCALE 0.18033688011112042f   // 0.125 * log2(e): scores in log2 domain

__global__ void __launch_bounds__(128, 3) gemm_qkv_kernel(
    const float* __restrict__ bq, const float* __restrict__ bk,
    const float* __restrict__ bv)
{
    extern __shared__ char smem[];
    const uint32_t smem_u = smem_to_u32(smem);

    const int tid = threadIdx.x, wid = tid >> 5, lane = tid & 31;
    const int mtile = blockIdx.y, ntile = blockIdx.x, z = blockIdx.z;
    const int wm = wid & 1, wn = wid >> 1;

    const __nv_bfloat16* Bh_g = g_Wht + (size_t)z * DD * DD;
    const __nv_bfloat16* Bl_g = g_Wlt + (size_t)z * DD * DD;
    const float* bias = (z == 0) ? bq : (z == 1) ? bk : bv;
    __nv_bfloat16* Ch = (z == 0) ? g_Qh : (z == 1) ? g_Kh : g_Vh;
    __nv_bfloat16* Cl = (z == 0) ? g_Ql : (z == 1) ? g_Kl : g_Vl;
    const float scale = (z == 0) ? QSCALE : 1.0f;

    float acc[2][8][4];
#pragma unroll
    for (int mi = 0; mi < 2; mi++)
#pragma unroll
        for (int ni = 0; ni < 8; ni++)
#pragma unroll
            for (int r = 0; r < 4; r++) acc[mi][ni][r] = 0.0f;

    gemm_mainloop(smem_u, tid, lane, wm, wn,
                  g_Xh + (size_t)mtile * 64 * DD,
                  g_Xl + (size_t)mtile * 64 * DD,
                  Bh_g + (size_t)ntile * 128 * DD,
                  Bl_g + (size_t)ntile * 128 * DD, acc);

    const int mb = mtile * 64 + wm * 32 + (lane >> 2);
    const int nb0 = ntile * 128 + wn * 64 + (lane & 3) * 2;

#pragma unroll
    for (int mi = 0; mi < 2; mi++)
#pragma unroll
        for (int ni = 0; ni < 8; ni++) {
            int n = nb0 + ni * 8;
            float2 bsv = *(const float2*)(bias + n);
            int hh2 = n >> 6, hd = n & 63;
#pragma unroll
            for (int half = 0; half < 2; half++) {
                int mg = mb + mi * 16 + half * 8;
                float v0 = (acc[mi][ni][half * 2 + 0] + bsv.x) * scale;
                float v1 = (acc[mi][ni][half * 2 + 1] + bsv.y) * scale;
                __nv_bfloat162 hp = __floats2bfloat162_rn(v0, v1);
                __nv_bfloat162 lp = __floats2bfloat162_rn(
                    v0 - __bfloat162float(hp.x), v1 - __bfloat162float(hp.y));
                int bq2 = mg >> 12, sseq = mg & 4095;
                size_t off = ((size_t)(bq2 * HH + hh2) * SS + sseq) * HD + hd;
                *(__nv_bfloat162*)(Ch + off) = hp;
                *(__nv_bfloat162*)(Cl + off) = lp;
            }
        }
}

// ---------------------------------------------------------------------------
// Output projection GEMM. grid (8, 128)
// ---------------------------------------------------------------------------
__global__ void __launch_bounds__(128, 3) gemm_out_kernel(
    const float* __restrict__ bo, float* __restrict__ Cf)
{
    extern __shared__ char smem[];
    const uint32_t smem_u = smem_to_u32(smem);

    const int tid = threadIdx.x, wid = tid >> 5, lane = tid & 31;
    const int mtile = blockIdx.y, ntile = blockIdx.x;
    const int wm = wid & 1, wn = wid >> 1;

    float acc[2][8][4];
#pragma unroll
    for (int mi = 0; mi < 2; mi++)
#pragma unroll
        for (int ni = 0; ni < 8; ni++)
#pragma unroll
            for (int r = 0; r < 4; r++) acc[mi][ni][r] = 0.0f;

    gemm_mainloop(smem_u, tid, lane, wm, wn,
                  g_Ah + (size_t)mtile * 64 * DD,
                  g_Al + (size_t)mtile * 64 * DD,
                  g_Wht + 3 * (size_t)DD * DD + (size_t)ntile * 128 * DD,
                  g_Wlt + 3 * (size_t)DD * DD + (size_t)ntile * 128 * DD, acc);

    const int mb = mtile * 64 + wm * 32 + (lane >> 2);
    const int nb0 = ntile * 128 + wn * 64 + (lane & 3) * 2;

#pragma unroll
    for (int mi = 0; mi < 2; mi++)
#pragma unroll
        for (int ni = 0; ni < 8; ni++) {
            int n = nb0 + ni * 8;
            float2 bsv = *(const float2*)(bo + n);
#pragma unroll
            for (int half = 0; half < 2; half++) {
                int m = mb + mi * 16 + half * 8;
                float2 o;
                o.x = acc[mi][ni][half * 2 + 0] + bsv.x;
                o.y = acc[mi][ni][half * 2 + 1] + bsv.y;
                *(float2*)(Cf + (size_t)m * DD + n) = o;
            }
        }
}

// ---------------------------------------------------------------------------
// Flash attention, TQ=64, 128 threads, 3 CTAs/SM (exact R10 winner).
// Prologue tweak: Q staged in buffer-1 region so KV(0) issues immediately
// after the Q loads (overlaps Q extraction with the first KV transfer).
// ---------------------------------------------------------------------------
#define TQ 64
#define TK 64
#define QST 72
#define QTILE_B (64 * QST * 2)       // 9216
#define KTILE_B (64 * QST * 2)       // 9216
#define ATTN_SMEM (2 * 4 * KTILE_B)  // 73728
#define NT (SS / TK)

__global__ void __launch_bounds__(128, 3) attn_mma_kernel()
{
    extern __shared__ char smem[];
    const uint32_t smem_u = smem_to_u32(smem);
    const uint32_t sBuf = smem_u;
    const uint32_t sQ = smem_u + 4 * KTILE_B;   // buffer-1 region

    const int tid = threadIdx.x, wid = tid >> 5, lane = tid & 31;
    const int b = blockIdx.z, h = blockIdx.y;
    const int q0 = blockIdx.x * TQ;
    const size_t bhoff = (size_t)(b * HH + h) * SS * HD;

    const __nv_bfloat16* kvsrc[4] = { g_Kh + bhoff, g_Kl + bhoff,
                                      g_Vh + bhoff, g_Vl + bhoff };
    auto issue_kv = [&](int t) {
        const uint32_t boff = sBuf + (uint32_t)(t & 1) * (4 * KTILE_B);
#pragma unroll
        for (int i = 0; i < 16; i++) {
            int seg = tid + i * 128;
            int arr = seg >> 9;
            int rem = seg & 511;
            int row = rem >> 3, g = rem & 7;
            cp_async16(boff + (uint32_t)arr * KTILE_B + (uint32_t)(row * QST + g * 8) * 2,
                       kvsrc[arr] + (size_t)(t * TK + row) * HD + g * 8);
        }
    };

    // Stage Q (hi+lo) into buffer-1 region; then immediately start KV(0)
    {
        const __nv_bfloat16* qsrc[2] = { g_Qh + bhoff + (size_t)q0 * HD,
                                         g_Ql + bhoff + (size_t)q0 * HD };
#pragma unroll
        for (int i = 0; i < 8; i++) {
            int seg = tid + i * 128;
            int arr = seg >> 9, rem = seg & 511;
            int row = rem >> 3, g = rem & 7;
            cp_async16(sQ + (uint32_t)arr * QTILE_B + (uint32_t)(row * QST + g * 8) * 2,
                       qsrc[arr] + (size_t)row * HD + g * 8);
        }
    }
    CP_COMMIT();            // group: Q
    issue_kv(0); CP_COMMIT();   // group: KV(0) into buffer 0
    CP_WAIT1();             // Q arrived (KV0 may still be in flight)
    __syncthreads();

    uint32_t qh[4][4], ql[4][4];
    {
        const int a_row = wid * 16 + (lane & 15);
        const int a_kof = (lane >> 4) * 8;
#pragma unroll
        for (int k = 0; k < 4; k++) {
            uint32_t ao = (uint32_t)(a_row * QST + k * 16 + a_kof) * 2;
            ldsm_x4(qh[k][0], qh[k][1], qh[k][2], qh[k][3], sQ + ao);
            ldsm_x4(ql[k][0], ql[k][1], ql[k][2], ql[k][3], sQ + QTILE_B + ao);
        }
    }
    __syncthreads();   // all warps extracted Q before buffer-1 is reused (t=1)

    float l0 = 0.0f, l1 = 0.0f;
    float o[8][4];
#pragma unroll
    for (int nb = 0; nb < 8; nb++)
#pragma unroll
        for (int r = 0; r < 4; r++) o[nb][r] = 0.0f;

    const int b_row = (lane & 7) + (lane >> 4) * 8;
    const int b_kof = ((lane >> 3) & 1) * 8;
    const int v_row = (lane & 15);
    const int v_col = (lane >> 4) * 8;

    for (int t = 0; t < NT; t++) {
        CP_WAIT0();
        __syncthreads();
        if (t < NT - 1) { issue_kv(t + 1); CP_COMMIT(); }

        const uint32_t boff = sBuf + (uint32_t)(t & 1) * (4 * KTILE_B);
        const uint32_t tKh = boff, tKl = boff + KTILE_B;
        const uint32_t tVh = boff + 2 * KTILE_B, tVl = boff + 3 * KTILE_B;

        float s[8][4];
#pragma unroll
        for (int nb = 0; nb < 8; nb++)
#pragma unroll
            for (int r = 0; r < 4; r++) s[nb][r] = 0.0f;

#pragma unroll
        for (int k = 0; k < 4; k++) {
            uint32_t kh[8][2], kl[8][2];
#pragma unroll
            for (int p = 0; p < 4; p++) {
                uint32_t bo = (uint32_t)((p * 16 + b_row) * QST + k * 16 + b_kof) * 2;
                ldsm_x4(kh[2 * p][0], kh[2 * p][1], kh[2 * p + 1][0], kh[2 * p + 1][1], tKh + bo);
                ldsm_x4(kl[2 * p][0], kl[2 * p][1], kl[2 * p + 1][0], kl[2 * p + 1][1], tKl + bo);
            }
#pragma unroll
            for (int nb = 0; nb < 8; nb++)
                mma16816(s[nb], qh[k], kh[nb]);   // hh
#pragma unroll
            for (int nb = 0; nb < 8; nb++)
                mma16816(s[nb], qh[k], kl[nb]);   // hl
#pragma unroll
            for (int nb = 0; nb < 8; nb++)
                mma16816(s[nb], ql[k], kh[nb]);   // lh
        }

#pragma unroll
        for (int j = 0; j < 4; j++) {
            float e00 = ex2(s[2 * j][0]),     e01 = ex2(s[2 * j][1]);
            float e02 = ex2(s[2 * j][2]),     e03 = ex2(s[2 * j][3]);
            float e10 = ex2(s[2 * j + 1][0]), e11 = ex2(s[2 * j + 1][1]);
            float e12 = ex2(s[2 * j + 1][2]), e13 = ex2(s[2 * j + 1][3]);
            l0 += e00 + e01 + e10 + e11;
            l1 += e02 + e03 + e12 + e13;

            uint32_t ph[4], pl[4];
            {
                float pv[4][2] = { {e00, e01}, {e02, e03}, {e10, e11}, {e12, e13} };
#pragma unroll
                for (int r = 0; r < 4; r++) {
                    __nv_bfloat162 hp = __floats2bfloat162_rn(pv[r][0], pv[r][1]);
                    __nv_bfloat162 lp = __floats2bfloat162_rn(
                        pv[r][0] - __bfloat162float(hp.x),
                        pv[r][1] - __bfloat162float(hp.y));
                    ph[r] = *reinterpret_cast<uint32_t*>(&hp);
                    pl[r] = *reinterpret_cast<uint32_t*>(&lp);
                }
            }
            uint32_t vh[8][2], vl[8][2];
#pragma unroll
            for (int p = 0; p < 4; p++) {
                uint32_t vo = (uint32_t)((j * 16 + v_row) * QST + p * 16 + v_col) * 2;
                ldsm_x4t(vh[2 * p][0], vh[2 * p][1], vh[2 * p + 1][0], vh[2 * p + 1][1], tVh + vo);
                ldsm_x4t(vl[2 * p][0], vl[2 * p][1], vl[2 * p + 1][0], vl[2 * p + 1][1], tVl + vo);
            }
#pragma unroll
            for (int nb = 0; nb < 8; nb++)
                mma16816(o[nb], ph, vh[nb]);   // hh
#pragma unroll
            for (int nb = 0; nb < 8; nb++)
                mma16816(o[nb], ph, vl[nb]);   // hl
#pragma unroll
            for (int nb = 0; nb < 8; nb++)
                mma16816(o[nb], pl, vh[nb]);   // lh
        }
    }

    l0 += __shfl_xor_sync(0xffffffffu, l0, 1);
    l0 += __shfl_xor_sync(0xffffffffu, l0, 2);
    l1 += __shfl_xor_sync(0xffffffffu, l1, 1);
    l1 += __shfl_xor_sync(0xffffffffu, l1, 2);
    const float inv0 = 1.0f / l0, inv1 = 1.0f / l1;

    const int qrow = q0 + wid * 16 + (lane >> 2);
    const size_t mrow0 = (size_t)(b * SS + qrow);
    const size_t mrow1 = mrow0 + 8;
    const int colb = h * HD + (lane & 3) * 2;
#pragma unroll
    for (int nb = 0; nb < 8; nb++) {
        int col = colb + nb * 8;
        float x0 = o[nb][0] * inv0, x1 = o[nb][1] * inv0;
        float x2 = o[nb][2] * inv1, x3 = o[nb][3] * inv1;
        __nv_bfloat162 h0 = __floats2bfloat162_rn(x0, x1);
        __nv_bfloat162 g0 = __floats2bfloat162_rn(
            x0 - __bfloat162float(h0.x), x1 - __bfloat162float(h0.y));
        __nv_bfloat162 h1 = __floats2bfloat162_rn(x2, x3);
        __nv_bfloat162 g1 = __floats2bfloat162_rn(
            x2 - __bfloat162float(h1.x), x3 - __bfloat162float(h1.y));
        *(__nv_bfloat162*)(g_Ah + mrow0 * DD + col) = h0;
        *(__nv_bfloat162*)(g_Al + mrow0 * DD + col) = g0;
        *(__nv_bfloat162*)(g_Ah + mrow1 * DD + col) = h1;
        *(__nv_bfloat162*)(g_Al + mrow1 * DD + col) = g1;
    }
}

// ---------------------------------------------------------------------------
// Launch
// ---------------------------------------------------------------------------
extern "C" void kernel_launch(void* const* d_in, const int* in_sizes, int n_in,
                              void* d_out, int out_size)
{
    (void)in_sizes; (void)n_in; (void)out_size;
    const float* X  = (const float*)d_in[0];
    const float* Wq = (const float*)d_in[1];
    const float* bq = (const float*)d_in[2];
    const float* Wk = (const float*)d_in[3];
    const float* bk = (const float*)d_in[4];
    const float* Wv = (const float*)d_in[5];
    const float* bv = (const float*)d_in[6];
    const float* Wo = (const float*)d_in[7];
    const float* bo = (const float*)d_in[8];
    float* out = (float*)d_out;

    __nv_bfloat16* pXh;
    __nv_bfloat16* pXl;
    cudaGetSymbolAddress((void**)&pXh, g_Xh);
    cudaGetSymbolAddress((void**)&pXl, g_Xl);

    cudaFuncSetAttribute(gemm_qkv_kernel,
                         cudaFuncAttributeMaxDynamicSharedMemorySize, GEMM_SMEM);
    cudaFuncSetAttribute(gemm_out_kernel,
                         cudaFuncAttributeMaxDynamicSharedMemorySize, GEMM_SMEM);
    cudaFuncSetAttribute(attn_mma_kernel,
                         cudaFuncAttributeMaxDynamicSharedMemorySize, ATTN_SMEM);

    xsplit_kernel<<<MM * DD / 4 / 256, 256>>>(X, pXh, pXl);
    dim3 gW(32, 32, 4), bW(32, 8);
    wsplit4_kernel<<<gW, bW>>>(Wq, Wk, Wv, Wo);

    dim3 gQKV(DD / 128, MM / 64, 3);    // (8, 128, 3)
    gemm_qkv_kernel<<<gQKV, 128, GEMM_SMEM>>>(bq, bk, bv);

    dim3 gattn(SS / TQ, HH, BB);        // (64, 16, 2)
    attn_mma_kernel<<<gattn, 128, ATTN_SMEM>>>();

    dim3 gO(DD / 128, MM / 64);         // (8, 128)
    gemm_out_kernel<<<gO, 128, GEMM_SMEM>>>(bo, out);
}

// round 17
// speedup vs baseline: 1.1824x; 1.0834x over previous
#include <cuda_runtime.h>
#include <cuda_bf16.h>
#include <cuda_fp16.h>
#include <cstdint>
#include <math.h>

// Problem constants
#define BB 2
#define SS 4096
#define DD 1024
#define HH 16
#define HD 64
#define MM (BB * SS)   // 8192

// ---------------------------------------------------------------------------
// Scratch (device globals)
// ---------------------------------------------------------------------------
__device__ __nv_bfloat16 g_Xh[MM * DD];
__device__ __nv_bfloat16 g_Xl[MM * DD];
__device__ __nv_bfloat16 g_Wht[4 * DD * DD];
__device__ __nv_bfloat16 g_Wlt[4 * DD * DD];
__device__ __nv_bfloat16 g_Qh[MM * DD];
__device__ __nv_bfloat16 g_Ql[MM * DD];
__device__ __nv_bfloat16 g_Kh[MM * DD];
__device__ __nv_bfloat16 g_Kl[MM * DD];
__device__ __half        g_Vh[MM * DD];     // V in fp16 hi/lo (PV precision path)
__device__ __half        g_Vl[MM * DD];
__device__ __nv_bfloat16 g_Ah[MM * DD];
__device__ __nv_bfloat16 g_Al[MM * DD];

// ---------------------------------------------------------------------------
// PTX helpers
// ---------------------------------------------------------------------------
__device__ __forceinline__ uint32_t smem_to_u32(const void* p) {
    uint32_t a;
    asm("{ .reg .u64 t; cvta.to.shared.u64 t, %1; cvt.u32.u64 %0, t; }"
        : "=r"(a) : "l"(p));
    return a;
}

__device__ __forceinline__ float ex2(float x) {
    float y;
    asm("ex2.approx.f32 %0, %1;" : "=f"(y) : "f"(x));
    return y;
}

__device__ __forceinline__ void cp_async16(uint32_t dst, const void* src) {
    asm volatile("cp.async.cg.shared.global [%0], [%1], 16;"
                 :: "r"(dst), "l"(src));
}
#define CP_COMMIT() asm volatile("cp.async.commit_group;" ::: "memory")
#define CP_WAIT1()  asm volatile("cp.async.wait_group 1;" ::: "memory")
#define CP_WAIT0()  asm volatile("cp.async.wait_group 0;" ::: "memory")

__device__ __forceinline__ void ldsm_x4(uint32_t& r0, uint32_t& r1,
                                        uint32_t& r2, uint32_t& r3, uint32_t addr) {
    asm volatile("ldmatrix.sync.aligned.m8n8.x4.shared.b16 {%0,%1,%2,%3}, [%4];"
                 : "=r"(r0), "=r"(r1), "=r"(r2), "=r"(r3) : "r"(addr));
}

__device__ __forceinline__ void ldsm_x4t(uint32_t& r0, uint32_t& r1,
                                         uint32_t& r2, uint32_t& r3, uint32_t addr) {
    asm volatile("ldmatrix.sync.aligned.m8n8.x4.trans.shared.b16 {%0,%1,%2,%3}, [%4];"
                 : "=r"(r0), "=r"(r1), "=r"(r2), "=r"(r3) : "r"(addr));
}

__device__ __forceinline__ void mma16816(float* c, const uint32_t* a, const uint32_t* b) {
    asm volatile(
        "mma.sync.aligned.m16n8k16.row.col.f32.bf16.bf16.f32 "
        "{%0,%1,%2,%3}, {%4,%5,%6,%7}, {%8,%9}, {%0,%1,%2,%3};"
        : "+f"(c[0]), "+f"(c[1]), "+f"(c[2]), "+f"(c[3])
        : "r"(a[0]), "r"(a[1]), "r"(a[2]), "r"(a[3]), "r"(b[0]), "r"(b[1]));
}

__device__ __forceinline__ void mma16816h(float* c, const uint32_t* a, const uint32_t* b) {
    asm volatile(
        "mma.sync.aligned.m16n8k16.row.col.f32.f16.f16.f32 "
        "{%0,%1,%2,%3}, {%4,%5,%6,%7}, {%8,%9}, {%0,%1,%2,%3};"
        : "+f"(c[0]), "+f"(c[1]), "+f"(c[2]), "+f"(c[3])
        : "r"(a[0]), "r"(a[1]), "r"(a[2]), "r"(a[3]), "r"(b[0]), "r"(b[1]));
}

// ---------------------------------------------------------------------------
// hi/lo bf16 split of X
// ---------------------------------------------------------------------------
__global__ void __launch_bounds__(256) xsplit_kernel(
    const float* __restrict__ X,
    __nv_bfloat16* __restrict__ Xh, __nv_bfloat16* __restrict__ Xl)
{
    int i = (blockIdx.x * 256 + threadIdx.x) * 4;
    float4 v = *(const float4*)(X + i);
    __nv_bfloat162 hp0 = __floats2bfloat162_rn(v.x, v.y);
    __nv_bfloat162 hp1 = __floats2bfloat162_rn(v.z, v.w);
    __nv_bfloat162 lp0 = __floats2bfloat162_rn(v.x - __bfloat162float(hp0.x),
                                               v.y - __bfloat162float(hp0.y));
    __nv_bfloat162 lp1 = __floats2bfloat162_rn(v.z - __bfloat162float(hp1.x),
                                               v.w - __bfloat162float(hp1.y));
    *(__nv_bfloat162*)(Xh + i)     = hp0;
    *(__nv_bfloat162*)(Xh + i + 2) = hp1;
    *(__nv_bfloat162*)(Xl + i)     = lp0;
    *(__nv_bfloat162*)(Xl + i + 2) = lp1;
}

// ---------------------------------------------------------------------------
// Transpose + split all 4 weights
// ---------------------------------------------------------------------------
__global__ void __launch_bounds__(256) wsplit4_kernel(
    const float* __restrict__ W0, const float* __restrict__ W1,
    const float* __restrict__ W2, const float* __restrict__ W3)
{
    __shared__ float t[32][33];
    const int z = blockIdx.z;
    const float* W = (z == 0) ? W0 : (z == 1) ? W1 : (z == 2) ? W2 : W3;
    __nv_bfloat16* Wht = g_Wht + (size_t)z * DD * DD;
    __nv_bfloat16* Wlt = g_Wlt + (size_t)z * DD * DD;

    int tx = threadIdx.x, ty = threadIdx.y;
    int n0 = blockIdx.x * 32, k0 = blockIdx.y * 32;
#pragma unroll
    for (int i = 0; i < 4; i++)
        t[ty + i * 8][tx] = W[(size_t)(k0 + ty + i * 8) * DD + n0 + tx];
    __syncthreads();
#pragma unroll
    for (int i = 0; i < 4; i++) {
        float v = t[tx][ty + i * 8];
        __nv_bfloat16 h = __float2bfloat16_rn(v);
        __nv_bfloat16 l = __float2bfloat16_rn(v - __bfloat162float(h));
        size_t idx = (size_t)(n0 + ty + i * 8) * DD + k0 + tx;
        Wht[idx] = h;
        Wlt[idx] = l;
    }
}

// ---------------------------------------------------------------------------
// GEMM mainloop (64x128 CTA tile, 128 threads, KC=32, double-buffered,
//   3 CTAs/SM, single barrier per chunk)
// ---------------------------------------------------------------------------
#define KC 32
#define GSTRIDE 40
#define TILE_A (64 * GSTRIDE * 2)
#define TILE_BB (128 * GSTRIDE * 2)
#define BUF_B  (2 * TILE_A + 2 * TILE_BB)
#define GEMM_SMEM (2 * BUF_B)            // 61440

__device__ __forceinline__ void gemm_mainloop(
    uint32_t smem_u, int tid, int lane, int wm, int wn,
    const __nv_bfloat16* ah_g, const __nv_bfloat16* al_g,
    const __nv_bfloat16* bh_g, const __nv_bfloat16* bl_g,
    float acc[2][8][4])
{
    auto issue_chunk = [&](int c) {
        const uint32_t boff = smem_u + (uint32_t)(c & 1) * BUF_B;
#pragma unroll
        for (int i = 0; i < 4; i++) {
            int seg = tid + i * 128;
            int t = seg >> 8;
            int rem = seg & 255;
            int row = rem >> 2, g = rem & 3;
            const __nv_bfloat16* src = t ? al_g : ah_g;
            cp_async16(boff + (uint32_t)t * TILE_A
                       + (uint32_t)(row * GSTRIDE + g * 8) * 2,
                       src + (size_t)row * DD + c * KC + g * 8);
        }
#pragma unroll
        for (int i = 0; i < 8; i++) {
            int seg = tid + i * 128;
            int t = seg >> 9;
            int rem = seg & 511;
            int row = rem >> 2, g = rem & 3;
            const __nv_bfloat16* src = t ? bl_g : bh_g;
            cp_async16(boff + 2 * TILE_A + (uint32_t)t * TILE_BB
                       + (uint32_t)(row * GSTRIDE + g * 8) * 2,
                       src + (size_t)row * DD + c * KC + g * 8);
        }
    };

    const int a_row = wm * 32 + (lane & 15);
    const int a_kof = (lane >> 4) * 8;
    const int b_row = wn * 64 + (lane & 7) + (lane >> 4) * 8;
    const int b_kof = ((lane >> 3) & 1) * 8;

    issue_chunk(0);
    CP_COMMIT();

    for (int c = 0; c < 32; c++) {
        CP_WAIT0();
        __syncthreads();
        if (c < 31) { issue_chunk(c + 1); CP_COMMIT(); }

        const uint32_t boff = smem_u + (uint32_t)(c & 1) * BUF_B;
        const uint32_t tAh = boff;
        const uint32_t tAl = boff + TILE_A;
        const uint32_t tBh = boff + 2 * TILE_A;
        const uint32_t tBl = boff + 2 * TILE_A + TILE_BB;

#pragma unroll
        for (int kb = 0; kb < KC; kb += 16) {
            uint32_t ah[2][4], al[2][4], bh[8][2], bl[8][2];
#pragma unroll
            for (int mi = 0; mi < 2; mi++) {
                uint32_t ao = (uint32_t)((a_row + mi * 16) * GSTRIDE + kb + a_kof) * 2;
                ldsm_x4(ah[mi][0], ah[mi][1], ah[mi][2], ah[mi][3], tAh + ao);
                ldsm_x4(al[mi][0], al[mi][1], al[mi][2], al[mi][3], tAl + ao);
            }
#pragma unroll
            for (int p = 0; p < 4; p++) {
                uint32_t bo = (uint32_t)((p * 16 + b_row) * GSTRIDE + kb + b_kof) * 2;
                ldsm_x4(bh[2 * p][0], bh[2 * p][1], bh[2 * p + 1][0], bh[2 * p + 1][1], tBh + bo);
                ldsm_x4(bl[2 * p][0], bl[2 * p][1], bl[2 * p + 1][0], bl[2 * p + 1][1], tBl + bo);
            }
#pragma unroll
            for (int mi = 0; mi < 2; mi++)
#pragma unroll
                for (int ni = 0; ni < 8; ni++)
                    mma16816(acc[mi][ni], ah[mi], bh[ni]);   // hh
#pragma unroll
            for (int mi = 0; mi < 2; mi++)
#pragma unroll
                for (int ni = 0; ni < 8; ni++)
                    mma16816(acc[mi][ni], ah[mi], bl[ni]);   // hl
#pragma unroll
            for (int mi = 0; mi < 2; mi++)
#pragma unroll
                for (int ni = 0; ni < 8; ni++)
                    mma16816(acc[mi][ni], al[mi], bh[ni]);   // lh
        }
    }
}

// ---------------------------------------------------------------------------
// Fused QKV projection GEMM. grid (8, 128, 3).
//   z==0/1: Q/K as bf16 hi/lo. z==2: V as fp16 hi/lo.
// ---------------------------------------------------------------------------
#define QSCALE 0.18033688011112042f   // 0.125 * log2(e): scores in log2 domain

__global__ void __launch_bounds__(128, 3) gemm_qkv_kernel(
    const float* __restrict__ bq, const float* __restrict__ bk,
    const float* __restrict__ bv)
{
    extern __shared__ char smem[];
    const uint32_t smem_u = smem_to_u32(smem);

    const int tid = threadIdx.x, wid = tid >> 5, lane = tid & 31;
    const int mtile = blockIdx.y, ntile = blockIdx.x, z = blockIdx.z;
    const int wm = wid & 1, wn = wid >> 1;

    const __nv_bfloat16* Bh_g = g_Wht + (size_t)z * DD * DD;
    const __nv_bfloat16* Bl_g = g_Wlt + (size_t)z * DD * DD;
    const float* bias = (z == 0) ? bq : (z == 1) ? bk : bv;
    const float scale = (z == 0) ? QSCALE : 1.0f;

    float acc[2][8][4];
#pragma unroll
    for (int mi = 0; mi < 2; mi++)
#pragma unroll
        for (int ni = 0; ni < 8; ni++)
#pragma unroll
            for (int r = 0; r < 4; r++) acc[mi][ni][r] = 0.0f;

    gemm_mainloop(smem_u, tid, lane, wm, wn,
                  g_Xh + (size_t)mtile * 64 * DD,
                  g_Xl + (size_t)mtile * 64 * DD,
                  Bh_g + (size_t)ntile * 128 * DD,
                  Bl_g + (size_t)ntile * 128 * DD, acc);

    const int mb = mtile * 64 + wm * 32 + (lane >> 2);
    const int nb0 = ntile * 128 + wn * 64 + (lane & 3) * 2;

#pragma unroll
    for (int mi = 0; mi < 2; mi++)
#pragma unroll
        for (int ni = 0; ni < 8; ni++) {
            int n = nb0 + ni * 8;
            float2 bsv = *(const float2*)(bias + n);
            int hh2 = n >> 6, hd = n & 63;
#pragma unroll
            for (int half = 0; half < 2; half++) {
                int mg = mb + mi * 16 + half * 8;
                float v0 = (acc[mi][ni][half * 2 + 0] + bsv.x) * scale;
                float v1 = (acc[mi][ni][half * 2 + 1] + bsv.y) * scale;
                int bq2 = mg >> 12, sseq = mg & 4095;
                size_t off = ((size_t)(bq2 * HH + hh2) * SS + sseq) * HD + hd;
                if (z == 2) {
                    __half2 hp = __floats2half2_rn(v0, v1);
                    __half2 lp = __floats2half2_rn(v0 - __half2float(__low2half(hp)),
                                                   v1 - __half2float(__high2half(hp)));
                    *(__half2*)(g_Vh + off) = hp;
                    *(__half2*)(g_Vl + off) = lp;
                } else {
                    __nv_bfloat16* Ch = (z == 0) ? g_Qh : g_Kh;
                    __nv_bfloat16* Cl = (z == 0) ? g_Ql : g_Kl;
                    __nv_bfloat162 hp = __floats2bfloat162_rn(v0, v1);
                    __nv_bfloat162 lp = __floats2bfloat162_rn(
                        v0 - __bfloat162float(hp.x), v1 - __bfloat162float(hp.y));
                    *(__nv_bfloat162*)(Ch + off) = hp;
                    *(__nv_bfloat162*)(Cl + off) = lp;
                }
            }
        }
}

// ---------------------------------------------------------------------------
// Output projection GEMM. grid (8, 128)
// ---------------------------------------------------------------------------
__global__ void __launch_bounds__(128, 3) gemm_out_kernel(
    const float* __restrict__ bo, float* __restrict__ Cf)
{
    extern __shared__ char smem[];
    const uint32_t smem_u = smem_to_u32(smem);

    const int tid = threadIdx.x, wid = tid >> 5, lane = tid & 31;
    const int mtile = blockIdx.y, ntile = blockIdx.x;
    const int wm = wid & 1, wn = wid >> 1;

    float acc[2][8][4];
#pragma unroll
    for (int mi = 0; mi < 2; mi++)
#pragma unroll
        for (int ni = 0; ni < 8; ni++)
#pragma unroll
            for (int r = 0; r < 4; r++) acc[mi][ni][r] = 0.0f;

    gemm_mainloop(smem_u, tid, lane, wm, wn,
                  g_Ah + (size_t)mtile * 64 * DD,
                  g_Al + (size_t)mtile * 64 * DD,
                  g_Wht + 3 * (size_t)DD * DD + (size_t)ntile * 128 * DD,
                  g_Wlt + 3 * (size_t)DD * DD + (size_t)ntile * 128 * DD, acc);

    const int mb = mtile * 64 + wm * 32 + (lane >> 2);
    const int nb0 = ntile * 128 + wn * 64 + (lane & 3) * 2;

#pragma unroll
    for (int mi = 0; mi < 2; mi++)
#pragma unroll
        for (int ni = 0; ni < 8; ni++) {
            int n = nb0 + ni * 8;
            float2 bsv = *(const float2*)(bo + n);
#pragma unroll
            for (int half = 0; half < 2; half++) {
                int m = mb + mi * 16 + half * 8;
                float2 o;
                o.x = acc[mi][ni][half * 2 + 0] + bsv.x;
                o.y = acc[mi][ni][half * 2 + 1] + bsv.y;
                *(float2*)(Cf + (size_t)m * DD + n) = o;
            }
        }
}

// ---------------------------------------------------------------------------
// Flash attention, TQ=64, 128 threads, 3 CTAs/SM.
// QK: bf16 3-term (score accuracy). PV: fp16 single P x fp16 V hi/lo (2 MMAs).
// Fixed-shift softmax, deferred l reduction. Q staged in buffer-1 region.
// ---------------------------------------------------------------------------
#define TQ 64
#define TK 64
#define QST 72
#define QTILE_B (64 * QST * 2)       // 9216
#define KTILE_B (64 * QST * 2)       // 9216
#define ATTN_SMEM (2 * 4 * KTILE_B)  // 73728
#define NT (SS / TK)

__global__ void __launch_bounds__(128, 3) attn_mma_kernel()
{
    extern __shared__ char smem[];
    const uint32_t smem_u = smem_to_u32(smem);
    const uint32_t sBuf = smem_u;
    const uint32_t sQ = smem_u + 4 * KTILE_B;   // buffer-1 region

    const int tid = threadIdx.x, wid = tid >> 5, lane = tid & 31;
    const int b = blockIdx.z, h = blockIdx.y;
    const int q0 = blockIdx.x * TQ;
    const size_t bhoff = (size_t)(b * HH + h) * SS * HD;

    const __nv_bfloat16* kvsrc[4] = {
        g_Kh + bhoff, g_Kl + bhoff,
        reinterpret_cast<const __nv_bfloat16*>(g_Vh) + bhoff,
        reinterpret_cast<const __nv_bfloat16*>(g_Vl) + bhoff };
    auto issue_kv = [&](int t) {
        const uint32_t boff = sBuf + (uint32_t)(t & 1) * (4 * KTILE_B);
#pragma unroll
        for (int i = 0; i < 16; i++) {
            int seg = tid + i * 128;
            int arr = seg >> 9;
            int rem = seg & 511;
            int row = rem >> 3, g = rem & 7;
            cp_async16(boff + (uint32_t)arr * KTILE_B + (uint32_t)(row * QST + g * 8) * 2,
                       kvsrc[arr] + (size_t)(t * TK + row) * HD + g * 8);
        }
    };

    // Stage Q (hi+lo) into buffer-1 region; then immediately start KV(0)
    {
        const __nv_bfloat16* qsrc[2] = { g_Qh + bhoff + (size_t)q0 * HD,
                                         g_Ql + bhoff + (size_t)q0 * HD };
#pragma unroll
        for (int i = 0; i < 8; i++) {
            int seg = tid + i * 128;
            int arr = seg >> 9, rem = seg & 511;
            int row = rem >> 3, g = rem & 7;
            cp_async16(sQ + (uint32_t)arr * QTILE_B + (uint32_t)(row * QST + g * 8) * 2,
                       qsrc[arr] + (size_t)row * HD + g * 8);
        }
    }
    CP_COMMIT();
    issue_kv(0); CP_COMMIT();
    CP_WAIT1();
    __syncthreads();

    uint32_t qh[4][4], ql[4][4];
    {
        const int a_row = wid * 16 + (lane & 15);
        const int a_kof = (lane >> 4) * 8;
#pragma unroll
        for (int k = 0; k < 4; k++) {
            uint32_t ao = (uint32_t)(a_row * QST + k * 16 + a_kof) * 2;
            ldsm_x4(qh[k][0], qh[k][1], qh[k][2], qh[k][3], sQ + ao);
            ldsm_x4(ql[k][0], ql[k][1], ql[k][2], ql[k][3], sQ + QTILE_B + ao);
        }
    }
    __syncthreads();

    float l0 = 0.0f, l1 = 0.0f;
    float o[8][4];
#pragma unroll
    for (int nb = 0; nb < 8; nb++)
#pragma unroll
        for (int r = 0; r < 4; r++) o[nb][r] = 0.0f;

    const int b_row = (lane & 7) + (lane >> 4) * 8;
    const int b_kof = ((lane >> 3) & 1) * 8;
    const int v_row = (lane & 15);
    const int v_col = (lane >> 4) * 8;

    for (int t = 0; t < NT; t++) {
        CP_WAIT0();
        __syncthreads();
        if (t < NT - 1) { issue_kv(t + 1); CP_COMMIT(); }

        const uint32_t boff = sBuf + (uint32_t)(t & 1) * (4 * KTILE_B);
        const uint32_t tKh = boff, tKl = boff + KTILE_B;
        const uint32_t tVh = boff + 2 * KTILE_B, tVl = boff + 3 * KTILE_B;

        // ---- S = Q K^T (bf16 3-term split) ----
        float s[8][4];
#pragma unroll
        for (int nb = 0; nb < 8; nb++)
#pragma unroll
            for (int r = 0; r < 4; r++) s[nb][r] = 0.0f;

#pragma unroll
        for (int k = 0; k < 4; k++) {
            uint32_t kh[8][2], kl[8][2];
#pragma unroll
            for (int p = 0; p < 4; p++) {
                uint32_t bo = (uint32_t)((p * 16 + b_row) * QST + k * 16 + b_kof) * 2;
                ldsm_x4(kh[2 * p][0], kh[2 * p][1], kh[2 * p + 1][0], kh[2 * p + 1][1], tKh + bo);
                ldsm_x4(kl[2 * p][0], kl[2 * p][1], kl[2 * p + 1][0], kl[2 * p + 1][1], tKl + bo);
            }
#pragma unroll
            for (int nb = 0; nb < 8; nb++)
                mma16816(s[nb], qh[k], kh[nb]);   // hh
#pragma unroll
            for (int nb = 0; nb < 8; nb++)
                mma16816(s[nb], qh[k], kl[nb]);   // hl
#pragma unroll
            for (int nb = 0; nb < 8; nb++)
                mma16816(s[nb], ql[k], kh[nb]);   // lh
        }

        // ---- P = 2^s (fixed shift), fp16 P; PV = P*Vh + P*Vl ----
#pragma unroll
        for (int j = 0; j < 4; j++) {
            float e00 = ex2(s[2 * j][0]),     e01 = ex2(s[2 * j][1]);
            float e02 = ex2(s[2 * j][2]),     e03 = ex2(s[2 * j][3]);
            float e10 = ex2(s[2 * j + 1][0]), e11 = ex2(s[2 * j + 1][1]);
            float e12 = ex2(s[2 * j + 1][2]), e13 = ex2(s[2 * j + 1][3]);
            l0 += e00 + e01 + e10 + e11;
            l1 += e02 + e03 + e12 + e13;

            uint32_t ph[4];
            {
                __half2 p0 = __floats2half2_rn(e00, e01);
                __half2 p1 = __floats2half2_rn(e02, e03);
                __half2 p2 = __floats2half2_rn(e10, e11);
                __half2 p3 = __floats2half2_rn(e12, e13);
                ph[0] = *reinterpret_cast<uint32_t*>(&p0);
                ph[1] = *reinterpret_cast<uint32_t*>(&p1);
                ph[2] = *reinterpret_cast<uint32_t*>(&p2);
                ph[3] = *reinterpret_cast<uint32_t*>(&p3);
            }
            uint32_t vh[8][2], vl[8][2];
#pragma unroll
            for (int p = 0; p < 4; p++) {
                uint32_t vo = (uint32_t)((j * 16 + v_row) * QST + p * 16 + v_col) * 2;
                ldsm_x4t(vh[2 * p][0], vh[2 * p][1], vh[2 * p + 1][0], vh[2 * p + 1][1], tVh + vo);
                ldsm_x4t(vl[2 * p][0], vl[2 * p][1], vl[2 * p + 1][0], vl[2 * p + 1][1], tVl + vo);
            }
#pragma unroll
            for (int nb = 0; nb < 8; nb++)
                mma16816h(o[nb], ph, vh[nb]);   // P * Vh
#pragma unroll
            for (int nb = 0; nb < 8; nb++)
                mma16816h(o[nb], ph, vl[nb]);   // P * Vl
        }
    }

    l0 += __shfl_xor_sync(0xffffffffu, l0, 1);
    l0 += __shfl_xor_sync(0xffffffffu, l0, 2);
    l1 += __shfl_xor_sync(0xffffffffu, l1, 1);
    l1 += __shfl_xor_sync(0xffffffffu, l1, 2);
    const float inv0 = 1.0f / l0, inv1 = 1.0f / l1;

    const int qrow = q0 + wid * 16 + (lane >> 2);
    const size_t mrow0 = (size_t)(b * SS + qrow);
    const size_t mrow1 = mrow0 + 8;
    const int colb = h * HD + (lane & 3) * 2;
#pragma unroll
    for (int nb = 0; nb < 8; nb++) {
        int col = colb + nb * 8;
        float x0 = o[nb][0] * inv0, x1 = o[nb][1] * inv0;
        float x2 = o[nb][2] * inv1, x3 = o[nb][3] * inv1;
        __nv_bfloat162 h0 = __floats2bfloat162_rn(x0, x1);
        __nv_bfloat162 g0 = __floats2bfloat162_rn(
            x0 - __bfloat162float(h0.x), x1 - __bfloat162float(h0.y));
        __nv_bfloat162 h1 = __floats2bfloat162_rn(x2, x3);
        __nv_bfloat162 g1 = __floats2bfloat162_rn(
            x2 - __bfloat162float(h1.x), x3 - __bfloat162float(h1.y));
        *(__nv_bfloat162*)(g_Ah + mrow0 * DD + col) = h0;
        *(__nv_bfloat162*)(g_Al + mrow0 * DD + col) = g0;
        *(__nv_bfloat162*)(g_Ah + mrow1 * DD + col) = h1;
        *(__nv_bfloat162*)(g_Al + mrow1 * DD + col) = g1;
    }
}

// ---------------------------------------------------------------------------
// Launch
// ---------------------------------------------------------------------------
extern "C" void kernel_launch(void* const* d_in, const int* in_sizes, int n_in,
                              void* d_out, int out_size)
{
    (void)in_sizes; (void)n_in; (void)out_size;
    const float* X  = (const float*)d_in[0];
    const float* Wq = (const float*)d_in[1];
    const float* bq = (const float*)d_in[2];
    const float* Wk = (const float*)d_in[3];
    const float* bk = (const float*)d_in[4];
    const float* Wv = (const float*)d_in[5];
    const float* bv = (const float*)d_in[6];
    const float* Wo = (const float*)d_in[7];
    const float* bo = (const float*)d_in[8];
    float* out = (float*)d_out;

    __nv_bfloat16* pXh;
    __nv_bfloat16* pXl;
    cudaGetSymbolAddress((void**)&pXh, g_Xh);
    cudaGetSymbolAddress((void**)&pXl, g_Xl);

    cudaFuncSetAttribute(gemm_qkv_kernel,
                         cudaFuncAttributeMaxDynamicSharedMemorySize, GEMM_SMEM);
    cudaFuncSetAttribute(gemm_out_kernel,
                         cudaFuncAttributeMaxDynamicSharedMemorySize, GEMM_SMEM);
    cudaFuncSetAttribute(attn_mma_kernel,
                         cudaFuncAttributeMaxDynamicSharedMemorySize, ATTN_SMEM);

    xsplit_kernel<<<MM * DD / 4 / 256, 256>>>(X, pXh, pXl);
    dim3 gW(32, 32, 4), bW(32, 8);
    wsplit4_kernel<<<gW, bW>>>(Wq, Wk, Wv, Wo);

    dim3 gQKV(DD / 128, MM / 64, 3);    // (8, 128, 3)
    gemm_qkv_kernel<<<gQKV, 128, GEMM_SMEM>>>(bq, bk, bv);

    dim3 gattn(SS / TQ, HH, BB);        // (64, 16, 2)
    attn_mma_kernel<<<gattn, 128, ATTN_SMEM>>>();

    dim3 gO(DD / 128, MM / 64);         // (8, 128)
    gemm_out_kernel<<<gO, 128, GEMM_SMEM>>>(bo, out);
}